// round 10
// baseline (speedup 1.0000x reference)
#include <cuda_runtime.h>
#include <cuda_bf16.h>
#include <cuda_fp16.h>
#include <cstdint>

#define SEQ    400
#define NHEADS 10
#define DK     64
#define NROWS  25600
#define DIM    640
#define CHUNK  (SEQ*DK)
#define NCHUNK ((NROWS/SEQ)*NHEADS)  // 640

// exp(s*0.125) = 2^(s*0.125*log2e); folded into Wq at convert time
#define QSCALE 0.180336878f

// Scratch (static __device__ arrays: the sanctioned no-alloc workaround)
__device__ float g_Y[(size_t)NROWS * DIM];
__device__ __nv_bfloat16 g_Xb[(size_t)NROWS * DIM];
__device__ __nv_bfloat16 g_Wb[(size_t)3 * DIM * DIM];
__device__ __nv_bfloat16 g_Qb[(size_t)NROWS * DIM];
__device__ __nv_bfloat16 g_Kb[(size_t)NROWS * DIM];
__device__ __half        g_Vh[(size_t)NROWS * DIM];

// ---------------------------------------------------------------------------
// helpers
// ---------------------------------------------------------------------------
__device__ __forceinline__ uint32_t smem_u32(const void* p) {
    uint32_t a;
    asm("{ .reg .u64 t; cvta.to.shared.u64 t, %1; cvt.u32.u64 %0, t; }" : "=r"(a) : "l"(p));
    return a;
}
#define SWZ128(o) ((o) ^ (((o) >> 3) & 0x70))

__device__ __forceinline__ void cp_async16(uint32_t dst, const void* src) {
    asm volatile("cp.async.cg.shared.global [%0], [%1], 16;" :: "r"(dst), "l"(src));
}
#define CP_COMMIT() asm volatile("cp.async.commit_group;" ::: "memory")
#define CP_WAIT(n)  asm volatile("cp.async.wait_group %0;" :: "n"(n) : "memory")

__device__ __forceinline__ void ldsm_x4(uint32_t* r, uint32_t addr) {
    asm volatile("ldmatrix.sync.aligned.m8n8.x4.shared.b16 {%0,%1,%2,%3}, [%4];"
                 : "=r"(r[0]), "=r"(r[1]), "=r"(r[2]), "=r"(r[3]) : "r"(addr));
}
__device__ __forceinline__ void ldsm_x4_t(uint32_t* r, uint32_t addr) {
    asm volatile("ldmatrix.sync.aligned.m8n8.x4.trans.shared.b16 {%0,%1,%2,%3}, [%4];"
                 : "=r"(r[0]), "=r"(r[1]), "=r"(r[2]), "=r"(r[3]) : "r"(addr));
}
__device__ __forceinline__ void mma_16816(float* c, const uint32_t* a,
                                          uint32_t b0, uint32_t b1) {
    asm volatile("mma.sync.aligned.m16n8k16.row.col.f32.bf16.bf16.f32 "
                 "{%0,%1,%2,%3}, {%4,%5,%6,%7}, {%8,%9}, {%0,%1,%2,%3};"
                 : "+f"(c[0]), "+f"(c[1]), "+f"(c[2]), "+f"(c[3])
                 : "r"(a[0]), "r"(a[1]), "r"(a[2]), "r"(a[3]), "r"(b0), "r"(b1));
}
__device__ __forceinline__ void mma_16816h(float* c, const uint32_t* a,
                                           uint32_t b0, uint32_t b1) {
    asm volatile("mma.sync.aligned.m16n8k16.row.col.f32.f16.f16.f32 "
                 "{%0,%1,%2,%3}, {%4,%5,%6,%7}, {%8,%9}, {%0,%1,%2,%3};"
                 : "+f"(c[0]), "+f"(c[1]), "+f"(c[2]), "+f"(c[3])
                 : "r"(a[0]), "r"(a[1]), "r"(a[2]), "r"(a[3]), "r"(b0), "r"(b1));
}
__device__ __forceinline__ uint32_t exp2_f16x2(float lo, float hi) {
    uint32_t h, r;
    asm("cvt.rn.f16x2.f32 %0, %1, %2;" : "=r"(h) : "f"(hi), "f"(lo));
    asm("ex2.approx.f16x2 %0, %1;" : "=r"(r) : "r"(h));
    return r;
}

// ---------------------------------------------------------------------------
// fp32 -> bf16 converts (GEMM inputs)
// ---------------------------------------------------------------------------
__global__ __launch_bounds__(256) void cvt_x(const float* __restrict__ x) {
    size_t i = ((size_t)blockIdx.x * 256 + threadIdx.x) * 8;
    float4 f0 = *(const float4*)(x + i);
    float4 f1 = *(const float4*)(x + i + 4);
    __nv_bfloat162 p0 = __floats2bfloat162_rn(f0.x, f0.y);
    __nv_bfloat162 p1 = __floats2bfloat162_rn(f0.z, f0.w);
    __nv_bfloat162 p2 = __floats2bfloat162_rn(f1.x, f1.y);
    __nv_bfloat162 p3 = __floats2bfloat162_rn(f1.z, f1.w);
    uint4 o;
    o.x = *(uint32_t*)&p0; o.y = *(uint32_t*)&p1;
    o.z = *(uint32_t*)&p2; o.w = *(uint32_t*)&p3;
    *(uint4*)(g_Xb + i) = o;
}

__global__ __launch_bounds__(256) void cvt_w(const float* __restrict__ Wq,
                                             const float* __restrict__ Wk,
                                             const float* __restrict__ Wv) {
    const float* W = (blockIdx.y == 0) ? Wq : (blockIdx.y == 1) ? Wk : Wv;
    const float s = (blockIdx.y == 0) ? QSCALE : 1.0f;
    size_t i = ((size_t)blockIdx.x * 256 + threadIdx.x) * 8;
    float4 f0 = *(const float4*)(W + i);
    float4 f1 = *(const float4*)(W + i + 4);
    __nv_bfloat162 p0 = __floats2bfloat162_rn(f0.x * s, f0.y * s);
    __nv_bfloat162 p1 = __floats2bfloat162_rn(f0.z * s, f0.w * s);
    __nv_bfloat162 p2 = __floats2bfloat162_rn(f1.x * s, f1.y * s);
    __nv_bfloat162 p3 = __floats2bfloat162_rn(f1.z * s, f1.w * s);
    uint4 o;
    o.x = *(uint32_t*)&p0; o.y = *(uint32_t*)&p1;
    o.z = *(uint32_t*)&p2; o.w = *(uint32_t*)&p3;
    *(uint4*)(g_Wb + (size_t)blockIdx.y * DIM * DIM + i) = o;
}

// ---------------------------------------------------------------------------
// QKV GEMM via mma.sync (HMMA bf16, fp32 accum) -> bf16 Q/K, f16 V.
// CTA tile 128x128, BK=64, 8 warps 4x2. 3-stage cp.async pipeline. 96KB smem.
// ---------------------------------------------------------------------------
#define GEMM_SMEM (3 * 32768)

__global__ __launch_bounds__(256, 2) void qkv_mma() {
    extern __shared__ char smem[];
    const int tid  = threadIdx.x;
    const int lane = tid & 31;
    const int wid  = tid >> 5;
    const int wm   = wid & 3;
    const int wn   = wid >> 2;
    const int z    = blockIdx.z;
    const int n0   = blockIdx.x * 128;
    const int m0   = blockIdx.y * 128;
    const __nv_bfloat16* Xpt = g_Xb + (size_t)n0 * DIM;
    const __nv_bfloat16* Wpt = g_Wb + (size_t)z * DIM * DIM + (size_t)m0 * DIM;
    const uint32_t sbase = smem_u32(smem);

    const int lr = tid >> 3;
    const int lcc = tid & 7;

    float acc[2][8][4];
#pragma unroll
    for (int i = 0; i < 2; ++i)
#pragma unroll
        for (int j = 0; j < 8; ++j)
#pragma unroll
            for (int k = 0; k < 4; ++k) acc[i][j][k] = 0.f;

    auto issue = [&](int c, int b) {
        const __nv_bfloat16* xs = Xpt + c * 64;
        const __nv_bfloat16* ws = Wpt + c * 64;
        const uint32_t stg = sbase + b * 32768;
#pragma unroll
        for (int i = 0; i < 4; ++i) {
            int r = lr + i * 32;
            uint32_t off = SWZ128(r * 128 + lcc * 16);
            cp_async16(stg + off, xs + (size_t)r * DIM + lcc * 8);
            cp_async16(stg + 16384 + off, ws + (size_t)r * DIM + lcc * 8);
        }
        CP_COMMIT();
    };

    issue(0, 0);
    issue(1, 1);

    const int arow = lane & 15;
    const int akb  = (lane >> 4) * 16;
    const int brow = (lane & 7) + ((lane >> 4) << 3);
    const int bkb  = ((lane >> 3) & 1) * 16;

    for (int c = 0; c < 10; ++c) {
        if (c == 9) { CP_WAIT(0); } else { CP_WAIT(1); }
        __syncthreads();
        if (c < 8) issue(c + 2, (c + 2) % 3);

        const uint32_t stg = sbase + (c % 3) * 32768;
        const uint32_t xb = stg;
        const uint32_t wb = stg + 16384;
#pragma unroll
        for (int ks = 0; ks < 4; ++ks) {
            uint32_t a[2][4];
#pragma unroll
            for (int i = 0; i < 2; ++i)
                ldsm_x4(a[i], xb + SWZ128((wm * 32 + i * 16 + arow) * 128 + ks * 32 + akb));
            uint32_t bf[4][4];
#pragma unroll
            for (int j = 0; j < 4; ++j)
                ldsm_x4(bf[j], wb + SWZ128((wn * 64 + j * 16 + brow) * 128 + ks * 32 + bkb));
#pragma unroll
            for (int i = 0; i < 2; ++i)
#pragma unroll
                for (int jj = 0; jj < 8; ++jj)
                    mma_16816(acc[i][jj], a[i], bf[jj >> 1][(jj & 1) * 2],
                              bf[jj >> 1][(jj & 1) * 2 + 1]);
        }
    }

    const int qr = lane >> 2;
    const int qc = (lane & 3) * 2;
    if (z == 2) {
        __half* Cz = g_Vh;
#pragma unroll
        for (int i = 0; i < 2; ++i)
#pragma unroll
            for (int jj = 0; jj < 8; ++jj) {
                int n = n0 + wm * 32 + i * 16 + qr;
                int m = m0 + wn * 64 + jj * 8 + qc;
                __half2 lo = __floats2half2_rn(acc[i][jj][0], acc[i][jj][1]);
                __half2 hi = __floats2half2_rn(acc[i][jj][2], acc[i][jj][3]);
                *(uint32_t*)&Cz[(size_t)n * DIM + m] = *(uint32_t*)&lo;
                *(uint32_t*)&Cz[(size_t)(n + 8) * DIM + m] = *(uint32_t*)&hi;
            }
    } else {
        __nv_bfloat16* Cz = (z == 0) ? g_Qb : g_Kb;
#pragma unroll
        for (int i = 0; i < 2; ++i)
#pragma unroll
            for (int jj = 0; jj < 8; ++jj) {
                int n = n0 + wm * 32 + i * 16 + qr;
                int m = m0 + wn * 64 + jj * 8 + qc;
                __nv_bfloat162 lo = __floats2bfloat162_rn(acc[i][jj][0], acc[i][jj][1]);
                __nv_bfloat162 hi = __floats2bfloat162_rn(acc[i][jj][2], acc[i][jj][3]);
                *(uint32_t*)&Cz[(size_t)n * DIM + m] = *(uint32_t*)&lo;
                *(uint32_t*)&Cz[(size_t)(n + 8) * DIM + m] = *(uint32_t*)&hi;
            }
    }
}

// ---------------------------------------------------------------------------
// FlashAttention-style attention via mma.sync, v6:
//  - software-pipelined: S(jc+1) interleaved with PV(jc); rotating 20-reg P
//  - 256 threads / 8 warps / 2 CTAs per SM; f16 PV HMMA; ex2.approx.f16x2
// ---------------------------------------------------------------------------
#define VOFF2 52224                  // 51*1024, 1024-aligned
#define ATT_SMEM (VOFF2 + 51200)     // 103424

__global__ __launch_bounds__(256, 2) void attn_mma(const float* __restrict__ x)
{
    extern __shared__ char sm[];
    const int tid  = threadIdx.x;
    const int lane = tid & 31;
    const int w    = tid >> 5;
    const int chunk = blockIdx.x;
    const size_t base = (size_t)chunk * CHUNK;
    const uint32_t KS = smem_u32(sm);
    const uint32_t VS = KS + VOFF2;

    // stage Km (raw-reshape layout [d][j], 816B padded rows) and V f16 (SW128)
    {
        const uint4* Kg = (const uint4*)(g_Kb + base);
        const uint4* Vg = (const uint4*)(g_Vh + base);
        for (int i = tid; i < 3200; i += 256) {
            int d = i / 50;
            int j = (i - d * 50) * 8;
            cp_async16(KS + d * 816 + j * 2, Kg + i);
            int row = i >> 3, cc = i & 7;
            cp_async16(VS + SWZ128(row * 128 + cc * 16), Vg + i);
        }
        CP_COMMIT();
        CP_WAIT(0);
    }
    __syncthreads();

    const int qr  = lane >> 2;
    const int l3  = lane & 3;
    const int l15 = lane & 15;
    const int lhi = lane >> 4;
    const uint32_t* Qg = (const uint32_t*)(g_Qb + base);

    for (int t = w; t < 25; t += 8) {
        const int q0 = t * 16;

        uint32_t aq[4][4];
        {
            const int r0i = (q0 + qr) * 32;
            const int r1i = r0i + 8 * 32;
#pragma unroll
            for (int kt = 0; kt < 4; ++kt) {
                aq[kt][0] = Qg[r0i + kt * 8 + l3];
                aq[kt][1] = Qg[r1i + kt * 8 + l3];
                aq[kt][2] = Qg[r0i + kt * 8 + l3 + 4];
                aq[kt][3] = Qg[r1i + kt * 8 + l3 + 4];
            }
        }

        float l0 = 0.f, l1 = 0.f;
        float o[8][4];
#pragma unroll
        for (int n = 0; n < 8; ++n)
#pragma unroll
            for (int k = 0; k < 4; ++k) o[n][k] = 0.f;

        uint32_t pa[20];          // rotating P fragments (current j-chunk)
        __half2 sum2a, sum2b;
        const __half2 hz = __floats2half2_rn(0.f, 0.f);

        // ---- S-phase prologue for jc = 0 ----
        sum2a = hz; sum2b = hz;
#pragma unroll
        for (int i = 0; i < 5; ++i) {
            float sA[4] = {0.f, 0.f, 0.f, 0.f};
            float sB[4] = {0.f, 0.f, 0.f, 0.f};
#pragma unroll
            for (int kt = 0; kt < 4; ++kt) {
                uint32_t b[4];
                ldsm_x4_t(b, KS + (kt * 16 + l15) * 816 + (i * 16 + lhi * 8) * 2);
                mma_16816(sA, aq[kt], b[0], b[1]);
                mma_16816(sB, aq[kt], b[2], b[3]);
            }
            uint32_t pA0 = exp2_f16x2(sA[0], sA[1]);
            uint32_t pA1 = exp2_f16x2(sA[2], sA[3]);
            uint32_t pB0 = exp2_f16x2(sB[0], sB[1]);
            uint32_t pB1 = exp2_f16x2(sB[2], sB[3]);
            sum2a = __hadd2(sum2a, *(__half2*)&pA0);
            sum2a = __hadd2(sum2a, *(__half2*)&pB0);
            sum2b = __hadd2(sum2b, *(__half2*)&pA1);
            sum2b = __hadd2(sum2b, *(__half2*)&pB1);
            pa[4 * i]     = pA0;
            pa[4 * i + 1] = pA1;
            pa[4 * i + 2] = pB0;
            pa[4 * i + 3] = pB1;
        }
        {
            float2 fa = __half22float2(sum2a);
            float2 fb = __half22float2(sum2b);
            l0 += fa.x + fa.y;
            l1 += fb.x + fb.y;
        }

        // ---- interleaved steady state: PV(jc-1) + S(jc), jc = 1..4 ----
#pragma unroll
        for (int jc = 1; jc < 5; ++jc) {
            const int jp = (jc - 1) * 80;
            const int j0 = jc * 80;
            sum2a = hz; sum2b = hz;
#pragma unroll
            for (int i = 0; i < 5; ++i) {
                // PV consuming pa[4i..4i+3] (previous chunk, j-tiles 2i,2i+1)
                {
                    uint32_t A[4] = { pa[4 * i], pa[4 * i + 1],
                                      pa[4 * i + 2], pa[4 * i + 3] };
                    const int krow = jp + i * 16 + l15;
#pragma unroll
                    for (int nn = 0; nn < 4; ++nn) {
                        uint32_t b[4];
                        ldsm_x4_t(b, VS + SWZ128(krow * 128 + nn * 32 + lhi * 16));
                        mma_16816h(o[nn * 2],     A, b[0], b[1]);
                        mma_16816h(o[nn * 2 + 1], A, b[2], b[3]);
                    }
                }
                // S producing pa[4i..4i+3] for current chunk
                {
                    float sA[4] = {0.f, 0.f, 0.f, 0.f};
                    float sB[4] = {0.f, 0.f, 0.f, 0.f};
#pragma unroll
                    for (int kt = 0; kt < 4; ++kt) {
                        uint32_t b[4];
                        ldsm_x4_t(b, KS + (kt * 16 + l15) * 816 +
                                     (j0 + i * 16 + lhi * 8) * 2);
                        mma_16816(sA, aq[kt], b[0], b[1]);
                        mma_16816(sB, aq[kt], b[2], b[3]);
                    }
                    uint32_t pA0 = exp2_f16x2(sA[0], sA[1]);
                    uint32_t pA1 = exp2_f16x2(sA[2], sA[3]);
                    uint32_t pB0 = exp2_f16x2(sB[0], sB[1]);
                    uint32_t pB1 = exp2_f16x2(sB[2], sB[3]);
                    sum2a = __hadd2(sum2a, *(__half2*)&pA0);
                    sum2a = __hadd2(sum2a, *(__half2*)&pB0);
                    sum2b = __hadd2(sum2b, *(__half2*)&pA1);
                    sum2b = __hadd2(sum2b, *(__half2*)&pB1);
                    pa[4 * i]     = pA0;
                    pa[4 * i + 1] = pA1;
                    pa[4 * i + 2] = pB0;
                    pa[4 * i + 3] = pB1;
                }
            }
            float2 fa = __half22float2(sum2a);
            float2 fb = __half22float2(sum2b);
            l0 += fa.x + fa.y;
            l1 += fb.x + fb.y;
        }

        // ---- PV epilogue for jc = 4 ----
        {
            const int jp = 320;
#pragma unroll
            for (int i = 0; i < 5; ++i) {
                uint32_t A[4] = { pa[4 * i], pa[4 * i + 1],
                                  pa[4 * i + 2], pa[4 * i + 3] };
                const int krow = jp + i * 16 + l15;
#pragma unroll
                for (int nn = 0; nn < 4; ++nn) {
                    uint32_t b[4];
                    ldsm_x4_t(b, VS + SWZ128(krow * 128 + nn * 32 + lhi * 16));
                    mma_16816h(o[nn * 2],     A, b[0], b[1]);
                    mma_16816h(o[nn * 2 + 1], A, b[2], b[3]);
                }
            }
        }

        l0 += __shfl_xor_sync(0xffffffffu, l0, 1);
        l0 += __shfl_xor_sync(0xffffffffu, l0, 2);
        l1 += __shfl_xor_sync(0xffffffffu, l1, 1);
        l1 += __shfl_xor_sync(0xffffffffu, l1, 2);
        const float i0 = 1.f / l0;
        const float i1 = 1.f / l1;
#pragma unroll
        for (int n = 0; n < 8; ++n) {
            int q = q0 + qr;
            int d = n * 8 + l3 * 2;
            size_t idx = base + (size_t)q * 64 + d;
            float2 xr = *(const float2*)&x[idx];
            float2 r0v = make_float2(o[n][0] * i0 + xr.x, o[n][1] * i0 + xr.y);
            *(float2*)&g_Y[idx] = r0v;
            size_t idx2 = idx + 8 * 64;
            float2 xr2 = *(const float2*)&x[idx2];
            float2 r1v = make_float2(o[n][2] * i1 + xr2.x, o[n][3] * i1 + xr2.y);
            *(float2*)&g_Y[idx2] = r1v;
        }
    }
}

// ---------------------------------------------------------------------------
// LayerNorm: one warp per row
// ---------------------------------------------------------------------------
__global__ __launch_bounds__(256) void ln_kernel(
    const float* __restrict__ gamma,
    const float* __restrict__ beta,
    float* __restrict__ out)
{
    const int lane = threadIdx.x & 31;
    const int w    = threadIdx.x >> 5;
    const int row  = blockIdx.x * 8 + w;
    const float* y = g_Y + (size_t)row * DIM;

    float4 v[5];
    float s = 0.f, sq = 0.f;
#pragma unroll
    for (int u = 0; u < 5; ++u) {
        v[u] = ((const float4*)y)[lane + 32 * u];
        s  += v[u].x + v[u].y + v[u].z + v[u].w;
        sq += v[u].x * v[u].x + v[u].y * v[u].y + v[u].z * v[u].z + v[u].w * v[u].w;
    }
#pragma unroll
    for (int o = 16; o > 0; o >>= 1) {
        s  += __shfl_xor_sync(0xffffffffu, s, o);
        sq += __shfl_xor_sync(0xffffffffu, sq, o);
    }
    const float mu  = s * (1.f / DIM);
    float var = sq * (1.f / DIM) - mu * mu;
    var = fmaxf(var, 0.f);
    const float rinv = rsqrtf(var + 1e-5f);

    float* orow = out + (size_t)row * DIM;
#pragma unroll
    for (int u = 0; u < 5; ++u) {
        float4 g4 = ((const float4*)gamma)[lane + 32 * u];
        float4 b4 = ((const float4*)beta)[lane + 32 * u];
        float4 o;
        o.x = (v[u].x - mu) * rinv * g4.x + b4.x;
        o.y = (v[u].y - mu) * rinv * g4.y + b4.y;
        o.z = (v[u].z - mu) * rinv * g4.z + b4.z;
        o.w = (v[u].w - mu) * rinv * g4.w + b4.w;
        ((float4*)orow)[lane + 32 * u] = o;
    }
}

// ---------------------------------------------------------------------------
extern "C" void kernel_launch(void* const* d_in, const int* in_sizes, int n_in,
                              void* d_out, int out_size)
{
    const float* x     = (const float*)d_in[0];
    const float* Wq    = (const float*)d_in[1];
    const float* Wk    = (const float*)d_in[2];
    const float* Wv    = (const float*)d_in[3];
    const float* gamma = (const float*)d_in[4];
    const float* beta  = (const float*)d_in[5];
    float* out = (float*)d_out;

    cudaFuncSetAttribute(qkv_mma, cudaFuncAttributeMaxDynamicSharedMemorySize, GEMM_SMEM);
    cudaFuncSetAttribute(attn_mma, cudaFuncAttributeMaxDynamicSharedMemorySize, ATT_SMEM);

    cvt_x<<<NROWS * DIM / (256 * 8), 256>>>(x);
    cvt_w<<<dim3(DIM * DIM / (256 * 8), 3), 256>>>(Wq, Wk, Wv);

    dim3 ggrid(NROWS / 128, DIM / 128, 3);
    qkv_mma<<<ggrid, 256, GEMM_SMEM>>>();

    attn_mma<<<NCHUNK, 256, ATT_SMEM>>>(x);

    ln_kernel<<<NROWS / 8, 256>>>(gamma, beta, out);
}

// round 11
// speedup vs baseline: 1.0270x; 1.0270x over previous
#include <cuda_runtime.h>
#include <cuda_bf16.h>
#include <cuda_fp16.h>
#include <cstdint>

#define SEQ    400
#define NHEADS 10
#define DK     64
#define NROWS  25600
#define DIM    640
#define CHUNK  (SEQ*DK)
#define NCHUNK ((NROWS/SEQ)*NHEADS)  // 640

// exp(s*0.125) = 2^(s*0.125*log2e); folded into Wq at convert time
#define QSCALE 0.180336878f

// Scratch (static __device__ arrays: the sanctioned no-alloc workaround)
__device__ float g_Y[(size_t)NROWS * DIM];
__device__ __nv_bfloat16 g_Xb[(size_t)NROWS * DIM];
__device__ __nv_bfloat16 g_Wb[(size_t)3 * DIM * DIM];
__device__ __nv_bfloat16 g_Qb[(size_t)NROWS * DIM];
__device__ __nv_bfloat16 g_Kb[(size_t)NROWS * DIM];
__device__ __half        g_Vh[(size_t)NROWS * DIM];

// ---------------------------------------------------------------------------
// helpers
// ---------------------------------------------------------------------------
__device__ __forceinline__ uint32_t smem_u32(const void* p) {
    uint32_t a;
    asm("{ .reg .u64 t; cvta.to.shared.u64 t, %1; cvt.u32.u64 %0, t; }" : "=r"(a) : "l"(p));
    return a;
}
#define SWZ128(o) ((o) ^ (((o) >> 3) & 0x70))

__device__ __forceinline__ void cp_async16(uint32_t dst, const void* src) {
    asm volatile("cp.async.cg.shared.global [%0], [%1], 16;" :: "r"(dst), "l"(src));
}
#define CP_COMMIT() asm volatile("cp.async.commit_group;" ::: "memory")
#define CP_WAIT(n)  asm volatile("cp.async.wait_group %0;" :: "n"(n) : "memory")

__device__ __forceinline__ void ldsm_x4(uint32_t* r, uint32_t addr) {
    asm volatile("ldmatrix.sync.aligned.m8n8.x4.shared.b16 {%0,%1,%2,%3}, [%4];"
                 : "=r"(r[0]), "=r"(r[1]), "=r"(r[2]), "=r"(r[3]) : "r"(addr));
}
__device__ __forceinline__ void ldsm_x4_t(uint32_t* r, uint32_t addr) {
    asm volatile("ldmatrix.sync.aligned.m8n8.x4.trans.shared.b16 {%0,%1,%2,%3}, [%4];"
                 : "=r"(r[0]), "=r"(r[1]), "=r"(r[2]), "=r"(r[3]) : "r"(addr));
}
__device__ __forceinline__ void mma_16816(float* c, const uint32_t* a,
                                          uint32_t b0, uint32_t b1) {
    asm volatile("mma.sync.aligned.m16n8k16.row.col.f32.bf16.bf16.f32 "
                 "{%0,%1,%2,%3}, {%4,%5,%6,%7}, {%8,%9}, {%0,%1,%2,%3};"
                 : "+f"(c[0]), "+f"(c[1]), "+f"(c[2]), "+f"(c[3])
                 : "r"(a[0]), "r"(a[1]), "r"(a[2]), "r"(a[3]), "r"(b0), "r"(b1));
}
__device__ __forceinline__ void mma_16816h(float* c, const uint32_t* a,
                                           uint32_t b0, uint32_t b1) {
    asm volatile("mma.sync.aligned.m16n8k16.row.col.f32.f16.f16.f32 "
                 "{%0,%1,%2,%3}, {%4,%5,%6,%7}, {%8,%9}, {%0,%1,%2,%3};"
                 : "+f"(c[0]), "+f"(c[1]), "+f"(c[2]), "+f"(c[3])
                 : "r"(a[0]), "r"(a[1]), "r"(a[2]), "r"(a[3]), "r"(b0), "r"(b1));
}
__device__ __forceinline__ uint32_t exp2_f16x2(float lo, float hi) {
    uint32_t h, r;
    asm("cvt.rn.f16x2.f32 %0, %1, %2;" : "=r"(h) : "f"(hi), "f"(lo));
    asm("ex2.approx.f16x2 %0, %1;" : "=r"(r) : "r"(h));
    return r;
}

// ---------------------------------------------------------------------------
// fused fp32 -> bf16 converts: x then Wq/Wk/Wv (one launch)
// grid.x = 8600 blocks: [0,8000) -> x, [8000,8600) -> W (200 blocks each)
// ---------------------------------------------------------------------------
__global__ __launch_bounds__(256) void cvt_all(const float* __restrict__ x,
                                               const float* __restrict__ Wq,
                                               const float* __restrict__ Wk,
                                               const float* __restrict__ Wv) {
    const size_t XB = 8000;            // x blocks
    const size_t WB = 200;             // blocks per W
    size_t b = blockIdx.x;
    const float* src;
    __nv_bfloat16* dst;
    float sc = 1.0f;
    size_t i;
    if (b < XB) {
        i = (b * 256 + threadIdx.x) * 8;
        src = x; dst = g_Xb;
    } else {
        size_t wb = b - XB;
        int z = (int)(wb / WB);
        i = ((wb - (size_t)z * WB) * 256 + threadIdx.x) * 8;
        src = (z == 0) ? Wq : (z == 1) ? Wk : Wv;
        dst = g_Wb + (size_t)z * DIM * DIM;
        if (z == 0) sc = QSCALE;
    }
    float4 f0 = *(const float4*)(src + i);
    float4 f1 = *(const float4*)(src + i + 4);
    __nv_bfloat162 p0 = __floats2bfloat162_rn(f0.x * sc, f0.y * sc);
    __nv_bfloat162 p1 = __floats2bfloat162_rn(f0.z * sc, f0.w * sc);
    __nv_bfloat162 p2 = __floats2bfloat162_rn(f1.x * sc, f1.y * sc);
    __nv_bfloat162 p3 = __floats2bfloat162_rn(f1.z * sc, f1.w * sc);
    uint4 o;
    o.x = *(uint32_t*)&p0; o.y = *(uint32_t*)&p1;
    o.z = *(uint32_t*)&p2; o.w = *(uint32_t*)&p3;
    *(uint4*)(dst + i) = o;
}

// ---------------------------------------------------------------------------
// QKV GEMM via mma.sync (HMMA bf16, fp32 accum) -> bf16 Q/K, f16 V.
// CTA tile 128x128, BK=64, 8 warps 4x2. 3-stage cp.async pipeline. 96KB smem.
// ---------------------------------------------------------------------------
#define GEMM_SMEM (3 * 32768)

__global__ __launch_bounds__(256, 2) void qkv_mma() {
    extern __shared__ char smem[];
    const int tid  = threadIdx.x;
    const int lane = tid & 31;
    const int wid  = tid >> 5;
    const int wm   = wid & 3;
    const int wn   = wid >> 2;
    const int z    = blockIdx.z;
    const int n0   = blockIdx.x * 128;
    const int m0   = blockIdx.y * 128;
    const __nv_bfloat16* Xpt = g_Xb + (size_t)n0 * DIM;
    const __nv_bfloat16* Wpt = g_Wb + (size_t)z * DIM * DIM + (size_t)m0 * DIM;
    const uint32_t sbase = smem_u32(smem);

    const int lr = tid >> 3;
    const int lcc = tid & 7;

    float acc[2][8][4];
#pragma unroll
    for (int i = 0; i < 2; ++i)
#pragma unroll
        for (int j = 0; j < 8; ++j)
#pragma unroll
            for (int k = 0; k < 4; ++k) acc[i][j][k] = 0.f;

    auto issue = [&](int c, int b) {
        const __nv_bfloat16* xs = Xpt + c * 64;
        const __nv_bfloat16* ws = Wpt + c * 64;
        const uint32_t stg = sbase + b * 32768;
#pragma unroll
        for (int i = 0; i < 4; ++i) {
            int r = lr + i * 32;
            uint32_t off = SWZ128(r * 128 + lcc * 16);
            cp_async16(stg + off, xs + (size_t)r * DIM + lcc * 8);
            cp_async16(stg + 16384 + off, ws + (size_t)r * DIM + lcc * 8);
        }
        CP_COMMIT();
    };

    issue(0, 0);
    issue(1, 1);

    const int arow = lane & 15;
    const int akb  = (lane >> 4) * 16;
    const int brow = (lane & 7) + ((lane >> 4) << 3);
    const int bkb  = ((lane >> 3) & 1) * 16;

    for (int c = 0; c < 10; ++c) {
        if (c == 9) { CP_WAIT(0); } else { CP_WAIT(1); }
        __syncthreads();
        if (c < 8) issue(c + 2, (c + 2) % 3);

        const uint32_t stg = sbase + (c % 3) * 32768;
        const uint32_t xb = stg;
        const uint32_t wb = stg + 16384;
#pragma unroll
        for (int ks = 0; ks < 4; ++ks) {
            uint32_t a[2][4];
#pragma unroll
            for (int i = 0; i < 2; ++i)
                ldsm_x4(a[i], xb + SWZ128((wm * 32 + i * 16 + arow) * 128 + ks * 32 + akb));
            uint32_t bf[4][4];
#pragma unroll
            for (int j = 0; j < 4; ++j)
                ldsm_x4(bf[j], wb + SWZ128((wn * 64 + j * 16 + brow) * 128 + ks * 32 + bkb));
#pragma unroll
            for (int i = 0; i < 2; ++i)
#pragma unroll
                for (int jj = 0; jj < 8; ++jj)
                    mma_16816(acc[i][jj], a[i], bf[jj >> 1][(jj & 1) * 2],
                              bf[jj >> 1][(jj & 1) * 2 + 1]);
        }
    }

    const int qr = lane >> 2;
    const int qc = (lane & 3) * 2;
    if (z == 2) {
        __half* Cz = g_Vh;
#pragma unroll
        for (int i = 0; i < 2; ++i)
#pragma unroll
            for (int jj = 0; jj < 8; ++jj) {
                int n = n0 + wm * 32 + i * 16 + qr;
                int m = m0 + wn * 64 + jj * 8 + qc;
                __half2 lo = __floats2half2_rn(acc[i][jj][0], acc[i][jj][1]);
                __half2 hi = __floats2half2_rn(acc[i][jj][2], acc[i][jj][3]);
                *(uint32_t*)&Cz[(size_t)n * DIM + m] = *(uint32_t*)&lo;
                *(uint32_t*)&Cz[(size_t)(n + 8) * DIM + m] = *(uint32_t*)&hi;
            }
    } else {
        __nv_bfloat16* Cz = (z == 0) ? g_Qb : g_Kb;
#pragma unroll
        for (int i = 0; i < 2; ++i)
#pragma unroll
            for (int jj = 0; jj < 8; ++jj) {
                int n = n0 + wm * 32 + i * 16 + qr;
                int m = m0 + wn * 64 + jj * 8 + qc;
                __nv_bfloat162 lo = __floats2bfloat162_rn(acc[i][jj][0], acc[i][jj][1]);
                __nv_bfloat162 hi = __floats2bfloat162_rn(acc[i][jj][2], acc[i][jj][3]);
                *(uint32_t*)&Cz[(size_t)n * DIM + m] = *(uint32_t*)&lo;
                *(uint32_t*)&Cz[(size_t)(n + 8) * DIM + m] = *(uint32_t*)&hi;
            }
    }
}

// ---------------------------------------------------------------------------
// FlashAttention-style attention via mma.sync, v7:
//  - grid (640, 2): each CTA does half the q-tiles (13 / 12) of one chunk
//    -> T_CTA halves, wave-quantization tail shrinks (3T -> ~2.25T)
//  - R9 inner structure (best measured): nn-outer S with fused exp, P
//    aliased into S regs; f16 PV HMMA; ex2.approx.f16x2 softmax
// ---------------------------------------------------------------------------
#define VOFF2 52224                  // 51*1024, 1024-aligned
#define ATT_SMEM (VOFF2 + 51200)     // 103424

__global__ __launch_bounds__(256, 2) void attn_mma(const float* __restrict__ x)
{
    extern __shared__ char sm[];
    const int tid  = threadIdx.x;
    const int lane = tid & 31;
    const int w    = tid >> 5;
    const int chunk = blockIdx.x;
    const int half  = blockIdx.y;
    const size_t base = (size_t)chunk * CHUNK;
    const uint32_t KS = smem_u32(sm);
    const uint32_t VS = KS + VOFF2;

    // stage Km (raw-reshape layout [d][j], 816B padded rows) and V f16 (SW128)
    {
        const uint4* Kg = (const uint4*)(g_Kb + base);
        const uint4* Vg = (const uint4*)(g_Vh + base);
        for (int i = tid; i < 3200; i += 256) {
            int d = i / 50;
            int j = (i - d * 50) * 8;
            cp_async16(KS + d * 816 + j * 2, Kg + i);
            int row = i >> 3, cc = i & 7;
            cp_async16(VS + SWZ128(row * 128 + cc * 16), Vg + i);
        }
        CP_COMMIT();
        CP_WAIT(0);
    }
    __syncthreads();

    const int qr  = lane >> 2;
    const int l3  = lane & 3;
    const int l15 = lane & 15;
    const int lhi = lane >> 4;
    const uint32_t* Qg = (const uint32_t*)(g_Qb + base);

    const int t_lo = half ? 13 : 0;
    const int t_hi = half ? 25 : 13;

    for (int t = t_lo + w; t < t_hi; t += 8) {
        const int q0 = t * 16;

        uint32_t aq[4][4];
        {
            const int r0i = (q0 + qr) * 32;
            const int r1i = r0i + 8 * 32;
#pragma unroll
            for (int kt = 0; kt < 4; ++kt) {
                aq[kt][0] = Qg[r0i + kt * 8 + l3];
                aq[kt][1] = Qg[r1i + kt * 8 + l3];
                aq[kt][2] = Qg[r0i + kt * 8 + l3 + 4];
                aq[kt][3] = Qg[r1i + kt * 8 + l3 + 4];
            }
        }

        float l0 = 0.f, l1 = 0.f;
        float o[8][4];
#pragma unroll
        for (int n = 0; n < 8; ++n)
#pragma unroll
            for (int k = 0; k < 4; ++k) o[n][k] = 0.f;

#pragma unroll
        for (int jc = 0; jc < 5; ++jc) {
            const int j0 = jc * 80;
            float s[10][4];
            uint32_t* pa = (uint32_t*)s;   // P frags alias S storage
            __half2 sum2a = __floats2half2_rn(0.f, 0.f);
            __half2 sum2b = sum2a;

            // S-phase: nn-outer, kt-inner; exp fused per nn
#pragma unroll
            for (int nn = 0; nn < 5; ++nn) {
                float* sA = s[nn * 2];
                float* sB = s[nn * 2 + 1];
#pragma unroll
                for (int k = 0; k < 4; ++k) { sA[k] = 0.f; sB[k] = 0.f; }
#pragma unroll
                for (int kt = 0; kt < 4; ++kt) {
                    uint32_t b[4];
                    ldsm_x4_t(b, KS + (kt * 16 + l15) * 816 +
                                 (j0 + nn * 16 + lhi * 8) * 2);
                    mma_16816(sA, aq[kt], b[0], b[1]);
                    mma_16816(sB, aq[kt], b[2], b[3]);
                }
                uint32_t pA0 = exp2_f16x2(sA[0], sA[1]);
                uint32_t pA1 = exp2_f16x2(sA[2], sA[3]);
                uint32_t pB0 = exp2_f16x2(sB[0], sB[1]);
                uint32_t pB1 = exp2_f16x2(sB[2], sB[3]);
                sum2a = __hadd2(sum2a, *(__half2*)&pA0);
                sum2a = __hadd2(sum2a, *(__half2*)&pB0);
                sum2b = __hadd2(sum2b, *(__half2*)&pA1);
                sum2b = __hadd2(sum2b, *(__half2*)&pB1);
                pa[(nn * 2) * 4]     = pA0;
                pa[(nn * 2) * 4 + 1] = pA1;
                pa[(nn * 2 + 1) * 4]     = pB0;
                pa[(nn * 2 + 1) * 4 + 1] = pB1;
            }
            float2 fa = __half22float2(sum2a);
            float2 fb = __half22float2(sum2b);
            l0 += fa.x + fa.y;
            l1 += fb.x + fb.y;

            // P @ V (f16 x f16)
#pragma unroll
            for (int kt = 0; kt < 5; ++kt) {
                uint32_t A[4] = { pa[(2 * kt) * 4], pa[(2 * kt) * 4 + 1],
                                  pa[(2 * kt + 1) * 4], pa[(2 * kt + 1) * 4 + 1] };
                const int krow = j0 + kt * 16 + l15;
#pragma unroll
                for (int nn = 0; nn < 4; ++nn) {
                    uint32_t b[4];
                    ldsm_x4_t(b, VS + SWZ128(krow * 128 + nn * 32 + lhi * 16));
                    mma_16816h(o[nn * 2],     A, b[0], b[1]);
                    mma_16816h(o[nn * 2 + 1], A, b[2], b[3]);
                }
            }
        }

        l0 += __shfl_xor_sync(0xffffffffu, l0, 1);
        l0 += __shfl_xor_sync(0xffffffffu, l0, 2);
        l1 += __shfl_xor_sync(0xffffffffu, l1, 1);
        l1 += __shfl_xor_sync(0xffffffffu, l1, 2);
        const float i0 = 1.f / l0;
        const float i1 = 1.f / l1;
#pragma unroll
        for (int n = 0; n < 8; ++n) {
            int q = q0 + qr;
            int d = n * 8 + l3 * 2;
            size_t idx = base + (size_t)q * 64 + d;
            float2 xr = *(const float2*)&x[idx];
            float2 r0v = make_float2(o[n][0] * i0 + xr.x, o[n][1] * i0 + xr.y);
            *(float2*)&g_Y[idx] = r0v;
            size_t idx2 = idx + 8 * 64;
            float2 xr2 = *(const float2*)&x[idx2];
            float2 r1v = make_float2(o[n][2] * i1 + xr2.x, o[n][3] * i1 + xr2.y);
            *(float2*)&g_Y[idx2] = r1v;
        }
    }
}

// ---------------------------------------------------------------------------
// LayerNorm: one warp per row
// ---------------------------------------------------------------------------
__global__ __launch_bounds__(256) void ln_kernel(
    const float* __restrict__ gamma,
    const float* __restrict__ beta,
    float* __restrict__ out)
{
    const int lane = threadIdx.x & 31;
    const int w    = threadIdx.x >> 5;
    const int row  = blockIdx.x * 8 + w;
    const float* y = g_Y + (size_t)row * DIM;

    float4 v[5];
    float s = 0.f, sq = 0.f;
#pragma unroll
    for (int u = 0; u < 5; ++u) {
        v[u] = ((const float4*)y)[lane + 32 * u];
        s  += v[u].x + v[u].y + v[u].z + v[u].w;
        sq += v[u].x * v[u].x + v[u].y * v[u].y + v[u].z * v[u].z + v[u].w * v[u].w;
    }
#pragma unroll
    for (int o = 16; o > 0; o >>= 1) {
        s  += __shfl_xor_sync(0xffffffffu, s, o);
        sq += __shfl_xor_sync(0xffffffffu, sq, o);
    }
    const float mu  = s * (1.f / DIM);
    float var = sq * (1.f / DIM) - mu * mu;
    var = fmaxf(var, 0.f);
    const float rinv = rsqrtf(var + 1e-5f);

    float* orow = out + (size_t)row * DIM;
#pragma unroll
    for (int u = 0; u < 5; ++u) {
        float4 g4 = ((const float4*)gamma)[lane + 32 * u];
        float4 b4 = ((const float4*)beta)[lane + 32 * u];
        float4 o;
        o.x = (v[u].x - mu) * rinv * g4.x + b4.x;
        o.y = (v[u].y - mu) * rinv * g4.y + b4.y;
        o.z = (v[u].z - mu) * rinv * g4.z + b4.z;
        o.w = (v[u].w - mu) * rinv * g4.w + b4.w;
        ((float4*)orow)[lane + 32 * u] = o;
    }
}

// ---------------------------------------------------------------------------
extern "C" void kernel_launch(void* const* d_in, const int* in_sizes, int n_in,
                              void* d_out, int out_size)
{
    const float* x     = (const float*)d_in[0];
    const float* Wq    = (const float*)d_in[1];
    const float* Wk    = (const float*)d_in[2];
    const float* Wv    = (const float*)d_in[3];
    const float* gamma = (const float*)d_in[4];
    const float* beta  = (const float*)d_in[5];
    float* out = (float*)d_out;

    cudaFuncSetAttribute(qkv_mma, cudaFuncAttributeMaxDynamicSharedMemorySize, GEMM_SMEM);
    cudaFuncSetAttribute(attn_mma, cudaFuncAttributeMaxDynamicSharedMemorySize, ATT_SMEM);

    cvt_all<<<8600, 256>>>(x, Wq, Wk, Wv);

    dim3 ggrid(NROWS / 128, DIM / 128, 3);
    qkv_mma<<<ggrid, 256, GEMM_SMEM>>>();

    dim3 agrid(NCHUNK, 2);
    attn_mma<<<agrid, 256, ATT_SMEM>>>(x);

    ln_kernel<<<NROWS / 8, 256>>>(gamma, beta, out);
}

// round 12
// speedup vs baseline: 1.0402x; 1.0128x over previous
#include <cuda_runtime.h>
#include <cuda_bf16.h>
#include <cuda_fp16.h>
#include <cstdint>

#define SEQ    400
#define NHEADS 10
#define DK     64
#define NROWS  25600
#define DIM    640
#define CHUNK  (SEQ*DK)
#define NCHUNK ((NROWS/SEQ)*NHEADS)  // 640

// exp(s*0.125) = 2^(s*0.125*log2e); folded into Wq at convert time
#define QSCALE 0.180336878f

// Scratch (static __device__ arrays: the sanctioned no-alloc workaround)
__device__ __half        g_Yh[(size_t)NROWS * DIM];   // f16 intermediate Y
__device__ __nv_bfloat16 g_Xb[(size_t)NROWS * DIM];
__device__ __nv_bfloat16 g_Wb[(size_t)3 * DIM * DIM];
__device__ __nv_bfloat16 g_Qb[(size_t)NROWS * DIM];
__device__ __nv_bfloat16 g_Kb[(size_t)NROWS * DIM];
__device__ __half        g_Vh[(size_t)NROWS * DIM];

// ---------------------------------------------------------------------------
// helpers
// ---------------------------------------------------------------------------
__device__ __forceinline__ uint32_t smem_u32(const void* p) {
    uint32_t a;
    asm("{ .reg .u64 t; cvta.to.shared.u64 t, %1; cvt.u32.u64 %0, t; }" : "=r"(a) : "l"(p));
    return a;
}
#define SWZ128(o) ((o) ^ (((o) >> 3) & 0x70))

__device__ __forceinline__ void cp_async16(uint32_t dst, const void* src) {
    asm volatile("cp.async.cg.shared.global [%0], [%1], 16;" :: "r"(dst), "l"(src));
}
#define CP_COMMIT() asm volatile("cp.async.commit_group;" ::: "memory")
#define CP_WAIT(n)  asm volatile("cp.async.wait_group %0;" :: "n"(n) : "memory")

__device__ __forceinline__ void ldsm_x4(uint32_t* r, uint32_t addr) {
    asm volatile("ldmatrix.sync.aligned.m8n8.x4.shared.b16 {%0,%1,%2,%3}, [%4];"
                 : "=r"(r[0]), "=r"(r[1]), "=r"(r[2]), "=r"(r[3]) : "r"(addr));
}
__device__ __forceinline__ void ldsm_x4_t(uint32_t* r, uint32_t addr) {
    asm volatile("ldmatrix.sync.aligned.m8n8.x4.trans.shared.b16 {%0,%1,%2,%3}, [%4];"
                 : "=r"(r[0]), "=r"(r[1]), "=r"(r[2]), "=r"(r[3]) : "r"(addr));
}
__device__ __forceinline__ void mma_16816(float* c, const uint32_t* a,
                                          uint32_t b0, uint32_t b1) {
    asm volatile("mma.sync.aligned.m16n8k16.row.col.f32.bf16.bf16.f32 "
                 "{%0,%1,%2,%3}, {%4,%5,%6,%7}, {%8,%9}, {%0,%1,%2,%3};"
                 : "+f"(c[0]), "+f"(c[1]), "+f"(c[2]), "+f"(c[3])
                 : "r"(a[0]), "r"(a[1]), "r"(a[2]), "r"(a[3]), "r"(b0), "r"(b1));
}
__device__ __forceinline__ void mma_16816h(float* c, const uint32_t* a,
                                           uint32_t b0, uint32_t b1) {
    asm volatile("mma.sync.aligned.m16n8k16.row.col.f32.f16.f16.f32 "
                 "{%0,%1,%2,%3}, {%4,%5,%6,%7}, {%8,%9}, {%0,%1,%2,%3};"
                 : "+f"(c[0]), "+f"(c[1]), "+f"(c[2]), "+f"(c[3])
                 : "r"(a[0]), "r"(a[1]), "r"(a[2]), "r"(a[3]), "r"(b0), "r"(b1));
}
__device__ __forceinline__ uint32_t exp2_f16x2(float lo, float hi) {
    uint32_t h, r;
    asm("cvt.rn.f16x2.f32 %0, %1, %2;" : "=r"(h) : "f"(hi), "f"(lo));
    asm("ex2.approx.f16x2 %0, %1;" : "=r"(r) : "r"(h));
    return r;
}

// ---------------------------------------------------------------------------
// fused fp32 -> bf16 converts: x then Wq/Wk/Wv (one launch)
// grid.x = 8600 blocks: [0,8000) -> x, [8000,8600) -> W (200 blocks each)
// ---------------------------------------------------------------------------
__global__ __launch_bounds__(256) void cvt_all(const float* __restrict__ x,
                                               const float* __restrict__ Wq,
                                               const float* __restrict__ Wk,
                                               const float* __restrict__ Wv) {
    const size_t XB = 8000;            // x blocks
    const size_t WB = 200;             // blocks per W
    size_t b = blockIdx.x;
    const float* src;
    __nv_bfloat16* dst;
    float sc = 1.0f;
    size_t i;
    if (b < XB) {
        i = (b * 256 + threadIdx.x) * 8;
        src = x; dst = g_Xb;
    } else {
        size_t wb = b - XB;
        int z = (int)(wb / WB);
        i = ((wb - (size_t)z * WB) * 256 + threadIdx.x) * 8;
        src = (z == 0) ? Wq : (z == 1) ? Wk : Wv;
        dst = g_Wb + (size_t)z * DIM * DIM;
        if (z == 0) sc = QSCALE;
    }
    float4 f0 = *(const float4*)(src + i);
    float4 f1 = *(const float4*)(src + i + 4);
    __nv_bfloat162 p0 = __floats2bfloat162_rn(f0.x * sc, f0.y * sc);
    __nv_bfloat162 p1 = __floats2bfloat162_rn(f0.z * sc, f0.w * sc);
    __nv_bfloat162 p2 = __floats2bfloat162_rn(f1.x * sc, f1.y * sc);
    __nv_bfloat162 p3 = __floats2bfloat162_rn(f1.z * sc, f1.w * sc);
    uint4 o;
    o.x = *(uint32_t*)&p0; o.y = *(uint32_t*)&p1;
    o.z = *(uint32_t*)&p2; o.w = *(uint32_t*)&p3;
    *(uint4*)(dst + i) = o;
}

// ---------------------------------------------------------------------------
// QKV GEMM via mma.sync (HMMA bf16, fp32 accum) -> bf16 Q/K, f16 V.
// CTA tile 128x128, BK=64, 8 warps 4x2. 3-stage cp.async pipeline. 96KB smem.
// ---------------------------------------------------------------------------
#define GEMM_SMEM (3 * 32768)

__global__ __launch_bounds__(256, 2) void qkv_mma() {
    extern __shared__ char smem[];
    const int tid  = threadIdx.x;
    const int lane = tid & 31;
    const int wid  = tid >> 5;
    const int wm   = wid & 3;
    const int wn   = wid >> 2;
    const int z    = blockIdx.z;
    const int n0   = blockIdx.x * 128;
    const int m0   = blockIdx.y * 128;
    const __nv_bfloat16* Xpt = g_Xb + (size_t)n0 * DIM;
    const __nv_bfloat16* Wpt = g_Wb + (size_t)z * DIM * DIM + (size_t)m0 * DIM;
    const uint32_t sbase = smem_u32(smem);

    const int lr = tid >> 3;
    const int lcc = tid & 7;

    float acc[2][8][4];
#pragma unroll
    for (int i = 0; i < 2; ++i)
#pragma unroll
        for (int j = 0; j < 8; ++j)
#pragma unroll
            for (int k = 0; k < 4; ++k) acc[i][j][k] = 0.f;

    auto issue = [&](int c, int b) {
        const __nv_bfloat16* xs = Xpt + c * 64;
        const __nv_bfloat16* ws = Wpt + c * 64;
        const uint32_t stg = sbase + b * 32768;
#pragma unroll
        for (int i = 0; i < 4; ++i) {
            int r = lr + i * 32;
            uint32_t off = SWZ128(r * 128 + lcc * 16);
            cp_async16(stg + off, xs + (size_t)r * DIM + lcc * 8);
            cp_async16(stg + 16384 + off, ws + (size_t)r * DIM + lcc * 8);
        }
        CP_COMMIT();
    };

    issue(0, 0);
    issue(1, 1);

    const int arow = lane & 15;
    const int akb  = (lane >> 4) * 16;
    const int brow = (lane & 7) + ((lane >> 4) << 3);
    const int bkb  = ((lane >> 3) & 1) * 16;

    for (int c = 0; c < 10; ++c) {
        if (c == 9) { CP_WAIT(0); } else { CP_WAIT(1); }
        __syncthreads();
        if (c < 8) issue(c + 2, (c + 2) % 3);

        const uint32_t stg = sbase + (c % 3) * 32768;
        const uint32_t xb = stg;
        const uint32_t wb = stg + 16384;
#pragma unroll
        for (int ks = 0; ks < 4; ++ks) {
            uint32_t a[2][4];
#pragma unroll
            for (int i = 0; i < 2; ++i)
                ldsm_x4(a[i], xb + SWZ128((wm * 32 + i * 16 + arow) * 128 + ks * 32 + akb));
            uint32_t bf[4][4];
#pragma unroll
            for (int j = 0; j < 4; ++j)
                ldsm_x4(bf[j], wb + SWZ128((wn * 64 + j * 16 + brow) * 128 + ks * 32 + bkb));
#pragma unroll
            for (int i = 0; i < 2; ++i)
#pragma unroll
                for (int jj = 0; jj < 8; ++jj)
                    mma_16816(acc[i][jj], a[i], bf[jj >> 1][(jj & 1) * 2],
                              bf[jj >> 1][(jj & 1) * 2 + 1]);
        }
    }

    const int qr = lane >> 2;
    const int qc = (lane & 3) * 2;
    if (z == 2) {
        __half* Cz = g_Vh;
#pragma unroll
        for (int i = 0; i < 2; ++i)
#pragma unroll
            for (int jj = 0; jj < 8; ++jj) {
                int n = n0 + wm * 32 + i * 16 + qr;
                int m = m0 + wn * 64 + jj * 8 + qc;
                __half2 lo = __floats2half2_rn(acc[i][jj][0], acc[i][jj][1]);
                __half2 hi = __floats2half2_rn(acc[i][jj][2], acc[i][jj][3]);
                *(uint32_t*)&Cz[(size_t)n * DIM + m] = *(uint32_t*)&lo;
                *(uint32_t*)&Cz[(size_t)(n + 8) * DIM + m] = *(uint32_t*)&hi;
            }
    } else {
        __nv_bfloat16* Cz = (z == 0) ? g_Qb : g_Kb;
#pragma unroll
        for (int i = 0; i < 2; ++i)
#pragma unroll
            for (int jj = 0; jj < 8; ++jj) {
                int n = n0 + wm * 32 + i * 16 + qr;
                int m = m0 + wn * 64 + jj * 8 + qc;
                __nv_bfloat162 lo = __floats2bfloat162_rn(acc[i][jj][0], acc[i][jj][1]);
                __nv_bfloat162 hi = __floats2bfloat162_rn(acc[i][jj][2], acc[i][jj][3]);
                *(uint32_t*)&Cz[(size_t)n * DIM + m] = *(uint32_t*)&lo;
                *(uint32_t*)&Cz[(size_t)(n + 8) * DIM + m] = *(uint32_t*)&hi;
            }
    }
}

// ---------------------------------------------------------------------------
// FlashAttention-style attention via mma.sync, v8:
//  - grid (640, 2): half the q-tiles (13 / 12) per CTA
//  - R9 inner structure; f16 PV HMMA; ex2.approx.f16x2 softmax
//  - epilogue writes f16 Y (vals + x in fp32, then cvt) -> halves Y traffic
// ---------------------------------------------------------------------------
#define VOFF2 52224                  // 51*1024, 1024-aligned
#define ATT_SMEM (VOFF2 + 51200)     // 103424

__global__ __launch_bounds__(256, 2) void attn_mma(const float* __restrict__ x)
{
    extern __shared__ char sm[];
    const int tid  = threadIdx.x;
    const int lane = tid & 31;
    const int w    = tid >> 5;
    const int chunk = blockIdx.x;
    const int half  = blockIdx.y;
    const size_t base = (size_t)chunk * CHUNK;
    const uint32_t KS = smem_u32(sm);
    const uint32_t VS = KS + VOFF2;

    // stage Km (raw-reshape layout [d][j], 816B padded rows) and V f16 (SW128)
    {
        const uint4* Kg = (const uint4*)(g_Kb + base);
        const uint4* Vg = (const uint4*)(g_Vh + base);
        for (int i = tid; i < 3200; i += 256) {
            int d = i / 50;
            int j = (i - d * 50) * 8;
            cp_async16(KS + d * 816 + j * 2, Kg + i);
            int row = i >> 3, cc = i & 7;
            cp_async16(VS + SWZ128(row * 128 + cc * 16), Vg + i);
        }
        CP_COMMIT();
        CP_WAIT(0);
    }
    __syncthreads();

    const int qr  = lane >> 2;
    const int l3  = lane & 3;
    const int l15 = lane & 15;
    const int lhi = lane >> 4;
    const uint32_t* Qg = (const uint32_t*)(g_Qb + base);

    const int t_lo = half ? 13 : 0;
    const int t_hi = half ? 25 : 13;

    for (int t = t_lo + w; t < t_hi; t += 8) {
        const int q0 = t * 16;

        uint32_t aq[4][4];
        {
            const int r0i = (q0 + qr) * 32;
            const int r1i = r0i + 8 * 32;
#pragma unroll
            for (int kt = 0; kt < 4; ++kt) {
                aq[kt][0] = Qg[r0i + kt * 8 + l3];
                aq[kt][1] = Qg[r1i + kt * 8 + l3];
                aq[kt][2] = Qg[r0i + kt * 8 + l3 + 4];
                aq[kt][3] = Qg[r1i + kt * 8 + l3 + 4];
            }
        }

        float l0 = 0.f, l1 = 0.f;
        float o[8][4];
#pragma unroll
        for (int n = 0; n < 8; ++n)
#pragma unroll
            for (int k = 0; k < 4; ++k) o[n][k] = 0.f;

#pragma unroll
        for (int jc = 0; jc < 5; ++jc) {
            const int j0 = jc * 80;
            float s[10][4];
            uint32_t* pa = (uint32_t*)s;   // P frags alias S storage
            __half2 sum2a = __floats2half2_rn(0.f, 0.f);
            __half2 sum2b = sum2a;

            // S-phase: nn-outer, kt-inner; exp fused per nn
#pragma unroll
            for (int nn = 0; nn < 5; ++nn) {
                float* sA = s[nn * 2];
                float* sB = s[nn * 2 + 1];
#pragma unroll
                for (int k = 0; k < 4; ++k) { sA[k] = 0.f; sB[k] = 0.f; }
#pragma unroll
                for (int kt = 0; kt < 4; ++kt) {
                    uint32_t b[4];
                    ldsm_x4_t(b, KS + (kt * 16 + l15) * 816 +
                                 (j0 + nn * 16 + lhi * 8) * 2);
                    mma_16816(sA, aq[kt], b[0], b[1]);
                    mma_16816(sB, aq[kt], b[2], b[3]);
                }
                uint32_t pA0 = exp2_f16x2(sA[0], sA[1]);
                uint32_t pA1 = exp2_f16x2(sA[2], sA[3]);
                uint32_t pB0 = exp2_f16x2(sB[0], sB[1]);
                uint32_t pB1 = exp2_f16x2(sB[2], sB[3]);
                sum2a = __hadd2(sum2a, *(__half2*)&pA0);
                sum2a = __hadd2(sum2a, *(__half2*)&pB0);
                sum2b = __hadd2(sum2b, *(__half2*)&pA1);
                sum2b = __hadd2(sum2b, *(__half2*)&pB1);
                pa[(nn * 2) * 4]     = pA0;
                pa[(nn * 2) * 4 + 1] = pA1;
                pa[(nn * 2 + 1) * 4]     = pB0;
                pa[(nn * 2 + 1) * 4 + 1] = pB1;
            }
            float2 fa = __half22float2(sum2a);
            float2 fb = __half22float2(sum2b);
            l0 += fa.x + fa.y;
            l1 += fb.x + fb.y;

            // P @ V (f16 x f16)
#pragma unroll
            for (int kt = 0; kt < 5; ++kt) {
                uint32_t A[4] = { pa[(2 * kt) * 4], pa[(2 * kt) * 4 + 1],
                                  pa[(2 * kt + 1) * 4], pa[(2 * kt + 1) * 4 + 1] };
                const int krow = j0 + kt * 16 + l15;
#pragma unroll
                for (int nn = 0; nn < 4; ++nn) {
                    uint32_t b[4];
                    ldsm_x4_t(b, VS + SWZ128(krow * 128 + nn * 32 + lhi * 16));
                    mma_16816h(o[nn * 2],     A, b[0], b[1]);
                    mma_16816h(o[nn * 2 + 1], A, b[2], b[3]);
                }
            }
        }

        l0 += __shfl_xor_sync(0xffffffffu, l0, 1);
        l0 += __shfl_xor_sync(0xffffffffu, l0, 2);
        l1 += __shfl_xor_sync(0xffffffffu, l1, 1);
        l1 += __shfl_xor_sync(0xffffffffu, l1, 2);
        const float i0 = 1.f / l0;
        const float i1 = 1.f / l1;
#pragma unroll
        for (int n = 0; n < 8; ++n) {
            int q = q0 + qr;
            int d = n * 8 + l3 * 2;
            size_t idx = base + (size_t)q * 64 + d;
            float2 xr = *(const float2*)&x[idx];
            __half2 y0 = __floats2half2_rn(o[n][0] * i0 + xr.x, o[n][1] * i0 + xr.y);
            *(uint32_t*)&g_Yh[idx] = *(uint32_t*)&y0;
            size_t idx2 = idx + 8 * 64;
            float2 xr2 = *(const float2*)&x[idx2];
            __half2 y1 = __floats2half2_rn(o[n][2] * i1 + xr2.x, o[n][3] * i1 + xr2.y);
            *(uint32_t*)&g_Yh[idx2] = *(uint32_t*)&y1;
        }
    }
}

// ---------------------------------------------------------------------------
// LayerNorm: one warp per row, f16 input, fp32 output
// lane loads 5 x uint2 (4 halves each): d = 4*lane + 128*u + 0..3
// ---------------------------------------------------------------------------
__global__ __launch_bounds__(256) void ln_kernel(
    const float* __restrict__ gamma,
    const float* __restrict__ beta,
    float* __restrict__ out)
{
    const int lane = threadIdx.x & 31;
    const int w    = threadIdx.x >> 5;
    const int row  = blockIdx.x * 8 + w;
    const uint2* y = (const uint2*)(g_Yh + (size_t)row * DIM);

    float4 v[5];
    float s = 0.f, sq = 0.f;
#pragma unroll
    for (int u = 0; u < 5; ++u) {
        uint2 raw = y[lane + 32 * u];
        float2 a = __half22float2(*(__half2*)&raw.x);
        float2 b = __half22float2(*(__half2*)&raw.y);
        v[u] = make_float4(a.x, a.y, b.x, b.y);
        s  += v[u].x + v[u].y + v[u].z + v[u].w;
        sq += v[u].x * v[u].x + v[u].y * v[u].y + v[u].z * v[u].z + v[u].w * v[u].w;
    }
#pragma unroll
    for (int o = 16; o > 0; o >>= 1) {
        s  += __shfl_xor_sync(0xffffffffu, s, o);
        sq += __shfl_xor_sync(0xffffffffu, sq, o);
    }
    const float mu  = s * (1.f / DIM);
    float var = sq * (1.f / DIM) - mu * mu;
    var = fmaxf(var, 0.f);
    const float rinv = rsqrtf(var + 1e-5f);

    float* orow = out + (size_t)row * DIM;
#pragma unroll
    for (int u = 0; u < 5; ++u) {
        float4 g4 = ((const float4*)gamma)[lane + 32 * u];
        float4 b4 = ((const float4*)beta)[lane + 32 * u];
        float4 o;
        o.x = (v[u].x - mu) * rinv * g4.x + b4.x;
        o.y = (v[u].y - mu) * rinv * g4.y + b4.y;
        o.z = (v[u].z - mu) * rinv * g4.z + b4.z;
        o.w = (v[u].w - mu) * rinv * g4.w + b4.w;
        ((float4*)orow)[lane + 32 * u] = o;
    }
}

// ---------------------------------------------------------------------------
extern "C" void kernel_launch(void* const* d_in, const int* in_sizes, int n_in,
                              void* d_out, int out_size)
{
    const float* x     = (const float*)d_in[0];
    const float* Wq    = (const float*)d_in[1];
    const float* Wk    = (const float*)d_in[2];
    const float* Wv    = (const float*)d_in[3];
    const float* gamma = (const float*)d_in[4];
    const float* beta  = (const float*)d_in[5];
    float* out = (float*)d_out;

    cudaFuncSetAttribute(qkv_mma, cudaFuncAttributeMaxDynamicSharedMemorySize, GEMM_SMEM);
    cudaFuncSetAttribute(attn_mma, cudaFuncAttributeMaxDynamicSharedMemorySize, ATT_SMEM);

    cvt_all<<<8600, 256>>>(x, Wq, Wk, Wv);

    dim3 ggrid(NROWS / 128, DIM / 128, 3);
    qkv_mma<<<ggrid, 256, GEMM_SMEM>>>();

    dim3 agrid(NCHUNK, 2);
    attn_mma<<<agrid, 256, ATT_SMEM>>>(x);

    ln_kernel<<<NROWS / 8, 256>>>(gamma, beta, out);
}

// round 13
// speedup vs baseline: 1.0466x; 1.0061x over previous
#include <cuda_runtime.h>
#include <cuda_bf16.h>
#include <cuda_fp16.h>
#include <cstdint>

#define SEQ    400
#define NHEADS 10
#define DK     64
#define NROWS  25600
#define DIM    640
#define CHUNK  (SEQ*DK)
#define NCHUNK ((NROWS/SEQ)*NHEADS)  // 640

// exp(s*0.125) = 2^(s*0.125*log2e); folded into Wq at convert time
#define QSCALE 0.180336878f

// Scratch (static __device__ arrays: the sanctioned no-alloc workaround)
__device__ __half        g_Yh[(size_t)NROWS * DIM];   // f16 intermediate Y
__device__ __nv_bfloat16 g_Xb[(size_t)NROWS * DIM];
__device__ __nv_bfloat16 g_Wb[(size_t)3 * DIM * DIM];
__device__ __half        g_Qh[(size_t)NROWS * DIM];
__device__ __half        g_Kh[(size_t)NROWS * DIM];
__device__ __half        g_Vh[(size_t)NROWS * DIM];

// ---------------------------------------------------------------------------
// helpers
// ---------------------------------------------------------------------------
__device__ __forceinline__ uint32_t smem_u32(const void* p) {
    uint32_t a;
    asm("{ .reg .u64 t; cvta.to.shared.u64 t, %1; cvt.u32.u64 %0, t; }" : "=r"(a) : "l"(p));
    return a;
}
#define SWZ128(o) ((o) ^ (((o) >> 3) & 0x70))

__device__ __forceinline__ void cp_async16(uint32_t dst, const void* src) {
    asm volatile("cp.async.cg.shared.global [%0], [%1], 16;" :: "r"(dst), "l"(src));
}
#define CP_COMMIT() asm volatile("cp.async.commit_group;" ::: "memory")
#define CP_WAIT(n)  asm volatile("cp.async.wait_group %0;" :: "n"(n) : "memory")

__device__ __forceinline__ void ldsm_x4(uint32_t* r, uint32_t addr) {
    asm volatile("ldmatrix.sync.aligned.m8n8.x4.shared.b16 {%0,%1,%2,%3}, [%4];"
                 : "=r"(r[0]), "=r"(r[1]), "=r"(r[2]), "=r"(r[3]) : "r"(addr));
}
__device__ __forceinline__ void ldsm_x4_t(uint32_t* r, uint32_t addr) {
    asm volatile("ldmatrix.sync.aligned.m8n8.x4.trans.shared.b16 {%0,%1,%2,%3}, [%4];"
                 : "=r"(r[0]), "=r"(r[1]), "=r"(r[2]), "=r"(r[3]) : "r"(addr));
}
// bf16 inputs, fp32 accum (QKV GEMM)
__device__ __forceinline__ void mma_16816(float* c, const uint32_t* a,
                                          uint32_t b0, uint32_t b1) {
    asm volatile("mma.sync.aligned.m16n8k16.row.col.f32.bf16.bf16.f32 "
                 "{%0,%1,%2,%3}, {%4,%5,%6,%7}, {%8,%9}, {%0,%1,%2,%3};"
                 : "+f"(c[0]), "+f"(c[1]), "+f"(c[2]), "+f"(c[3])
                 : "r"(a[0]), "r"(a[1]), "r"(a[2]), "r"(a[3]), "r"(b0), "r"(b1));
}
// f16 inputs, f16 accum (attention; 2x tensor rate, packed D)
__device__ __forceinline__ void mma_16816hh(uint32_t* c, const uint32_t* a,
                                            uint32_t b0, uint32_t b1) {
    asm volatile("mma.sync.aligned.m16n8k16.row.col.f16.f16.f16.f16 "
                 "{%0,%1}, {%2,%3,%4,%5}, {%6,%7}, {%0,%1};"
                 : "+r"(c[0]), "+r"(c[1])
                 : "r"(a[0]), "r"(a[1]), "r"(a[2]), "r"(a[3]), "r"(b0), "r"(b1));
}
__device__ __forceinline__ uint32_t ex2h2(uint32_t h) {
    uint32_t r;
    asm("ex2.approx.f16x2 %0, %1;" : "=r"(r) : "r"(h));
    return r;
}

// ---------------------------------------------------------------------------
// fused fp32 -> bf16 converts: x then Wq/Wk/Wv (one launch)
// ---------------------------------------------------------------------------
__global__ __launch_bounds__(256) void cvt_all(const float* __restrict__ x,
                                               const float* __restrict__ Wq,
                                               const float* __restrict__ Wk,
                                               const float* __restrict__ Wv) {
    const size_t XB = 8000;
    const size_t WB = 200;
    size_t b = blockIdx.x;
    const float* src;
    __nv_bfloat16* dst;
    float sc = 1.0f;
    size_t i;
    if (b < XB) {
        i = (b * 256 + threadIdx.x) * 8;
        src = x; dst = g_Xb;
    } else {
        size_t wb = b - XB;
        int z = (int)(wb / WB);
        i = ((wb - (size_t)z * WB) * 256 + threadIdx.x) * 8;
        src = (z == 0) ? Wq : (z == 1) ? Wk : Wv;
        dst = g_Wb + (size_t)z * DIM * DIM;
        if (z == 0) sc = QSCALE;
    }
    float4 f0 = *(const float4*)(src + i);
    float4 f1 = *(const float4*)(src + i + 4);
    __nv_bfloat162 p0 = __floats2bfloat162_rn(f0.x * sc, f0.y * sc);
    __nv_bfloat162 p1 = __floats2bfloat162_rn(f0.z * sc, f0.w * sc);
    __nv_bfloat162 p2 = __floats2bfloat162_rn(f1.x * sc, f1.y * sc);
    __nv_bfloat162 p3 = __floats2bfloat162_rn(f1.z * sc, f1.w * sc);
    uint4 o;
    o.x = *(uint32_t*)&p0; o.y = *(uint32_t*)&p1;
    o.z = *(uint32_t*)&p2; o.w = *(uint32_t*)&p3;
    *(uint4*)(dst + i) = o;
}

// ---------------------------------------------------------------------------
// QKV GEMM via mma.sync (HMMA bf16, fp32 accum) -> f16 Q/K/V.
// CTA tile 128x128, BK=64, 8 warps 4x2. 3-stage cp.async pipeline. 96KB smem.
// ---------------------------------------------------------------------------
#define GEMM_SMEM (3 * 32768)

__global__ __launch_bounds__(256, 2) void qkv_mma() {
    extern __shared__ char smem[];
    const int tid  = threadIdx.x;
    const int lane = tid & 31;
    const int wid  = tid >> 5;
    const int wm   = wid & 3;
    const int wn   = wid >> 2;
    const int z    = blockIdx.z;
    const int n0   = blockIdx.x * 128;
    const int m0   = blockIdx.y * 128;
    const __nv_bfloat16* Xpt = g_Xb + (size_t)n0 * DIM;
    const __nv_bfloat16* Wpt = g_Wb + (size_t)z * DIM * DIM + (size_t)m0 * DIM;
    const uint32_t sbase = smem_u32(smem);

    const int lr = tid >> 3;
    const int lcc = tid & 7;

    float acc[2][8][4];
#pragma unroll
    for (int i = 0; i < 2; ++i)
#pragma unroll
        for (int j = 0; j < 8; ++j)
#pragma unroll
            for (int k = 0; k < 4; ++k) acc[i][j][k] = 0.f;

    auto issue = [&](int c, int b) {
        const __nv_bfloat16* xs = Xpt + c * 64;
        const __nv_bfloat16* ws = Wpt + c * 64;
        const uint32_t stg = sbase + b * 32768;
#pragma unroll
        for (int i = 0; i < 4; ++i) {
            int r = lr + i * 32;
            uint32_t off = SWZ128(r * 128 + lcc * 16);
            cp_async16(stg + off, xs + (size_t)r * DIM + lcc * 8);
            cp_async16(stg + 16384 + off, ws + (size_t)r * DIM + lcc * 8);
        }
        CP_COMMIT();
    };

    issue(0, 0);
    issue(1, 1);

    const int arow = lane & 15;
    const int akb  = (lane >> 4) * 16;
    const int brow = (lane & 7) + ((lane >> 4) << 3);
    const int bkb  = ((lane >> 3) & 1) * 16;

    for (int c = 0; c < 10; ++c) {
        if (c == 9) { CP_WAIT(0); } else { CP_WAIT(1); }
        __syncthreads();
        if (c < 8) issue(c + 2, (c + 2) % 3);

        const uint32_t stg = sbase + (c % 3) * 32768;
        const uint32_t xb = stg;
        const uint32_t wb = stg + 16384;
#pragma unroll
        for (int ks = 0; ks < 4; ++ks) {
            uint32_t a[2][4];
#pragma unroll
            for (int i = 0; i < 2; ++i)
                ldsm_x4(a[i], xb + SWZ128((wm * 32 + i * 16 + arow) * 128 + ks * 32 + akb));
            uint32_t bf[4][4];
#pragma unroll
            for (int j = 0; j < 4; ++j)
                ldsm_x4(bf[j], wb + SWZ128((wn * 64 + j * 16 + brow) * 128 + ks * 32 + bkb));
#pragma unroll
            for (int i = 0; i < 2; ++i)
#pragma unroll
                for (int jj = 0; jj < 8; ++jj)
                    mma_16816(acc[i][jj], a[i], bf[jj >> 1][(jj & 1) * 2],
                              bf[jj >> 1][(jj & 1) * 2 + 1]);
        }
    }

    const int qr = lane >> 2;
    const int qc = (lane & 3) * 2;
    __half* Cz = (z == 0) ? g_Qh : (z == 1) ? g_Kh : g_Vh;
#pragma unroll
    for (int i = 0; i < 2; ++i)
#pragma unroll
        for (int jj = 0; jj < 8; ++jj) {
            int n = n0 + wm * 32 + i * 16 + qr;
            int m = m0 + wn * 64 + jj * 8 + qc;
            __half2 lo = __floats2half2_rn(acc[i][jj][0], acc[i][jj][1]);
            __half2 hi = __floats2half2_rn(acc[i][jj][2], acc[i][jj][3]);
            *(uint32_t*)&Cz[(size_t)n * DIM + m] = *(uint32_t*)&lo;
            *(uint32_t*)&Cz[(size_t)(n + 8) * DIM + m] = *(uint32_t*)&hi;
        }
}

// ---------------------------------------------------------------------------
// FlashAttention-style attention via mma.sync, v9:
//  - ALL f16: f16-accum HMMA for S and PV (2x tensor rate, packed D frags)
//  - S D-frags are f16x2 -> ex2.approx.f16x2 applied directly, result IS the
//    PV A-frag (packed layouts line up); O accumulated in f16x2 (16 regs)
//  - grid (640, 2): half the q-tiles per CTA; f16 Y epilogue
// ---------------------------------------------------------------------------
#define VOFF2 52224                  // 51*1024, 1024-aligned
#define ATT_SMEM (VOFF2 + 51200)     // 103424

__global__ __launch_bounds__(256, 2) void attn_mma(const float* __restrict__ x)
{
    extern __shared__ char sm[];
    const int tid  = threadIdx.x;
    const int lane = tid & 31;
    const int w    = tid >> 5;
    const int chunk = blockIdx.x;
    const int half  = blockIdx.y;
    const size_t base = (size_t)chunk * CHUNK;
    const uint32_t KS = smem_u32(sm);
    const uint32_t VS = KS + VOFF2;

    // stage Km (raw-reshape layout [d][j], 816B padded rows) and V f16 (SW128)
    {
        const uint4* Kg = (const uint4*)(g_Kh + base);
        const uint4* Vg = (const uint4*)(g_Vh + base);
        for (int i = tid; i < 3200; i += 256) {
            int d = i / 50;
            int j = (i - d * 50) * 8;
            cp_async16(KS + d * 816 + j * 2, Kg + i);
            int row = i >> 3, cc = i & 7;
            cp_async16(VS + SWZ128(row * 128 + cc * 16), Vg + i);
        }
        CP_COMMIT();
        CP_WAIT(0);
    }
    __syncthreads();

    const int qr  = lane >> 2;
    const int l3  = lane & 3;
    const int l15 = lane & 15;
    const int lhi = lane >> 4;
    const uint32_t* Qg = (const uint32_t*)(g_Qh + base);

    const int t_lo = half ? 13 : 0;
    const int t_hi = half ? 25 : 13;

    for (int t = t_lo + w; t < t_hi; t += 8) {
        const int q0 = t * 16;

        uint32_t aq[4][4];
        {
            const int r0i = (q0 + qr) * 32;
            const int r1i = r0i + 8 * 32;
#pragma unroll
            for (int kt = 0; kt < 4; ++kt) {
                aq[kt][0] = Qg[r0i + kt * 8 + l3];
                aq[kt][1] = Qg[r1i + kt * 8 + l3];
                aq[kt][2] = Qg[r0i + kt * 8 + l3 + 4];
                aq[kt][3] = Qg[r1i + kt * 8 + l3 + 4];
            }
        }

        float l0 = 0.f, l1 = 0.f;
        uint32_t oh[16];               // f16x2 O accum: tile n -> oh[2n],oh[2n+1]
#pragma unroll
        for (int n = 0; n < 16; ++n) oh[n] = 0u;

#pragma unroll
        for (int jc = 0; jc < 5; ++jc) {
            const int j0 = jc * 80;
            uint32_t pa[20];           // P frags: nn -> pa[4nn..4nn+3]
            __half2 sum2a = __floats2half2_rn(0.f, 0.f);
            __half2 sum2b = sum2a;

            // S-phase: per nn, 2 f16-accum MMAs (n8 tiles j..j+7, j+8..j+15)
#pragma unroll
            for (int nn = 0; nn < 5; ++nn) {
                uint32_t s0[2] = {0u, 0u};
                uint32_t s1[2] = {0u, 0u};
#pragma unroll
                for (int kt = 0; kt < 4; ++kt) {
                    uint32_t b[4];
                    ldsm_x4_t(b, KS + (kt * 16 + l15) * 816 +
                                 (j0 + nn * 16 + lhi * 8) * 2);
                    mma_16816hh(s0, aq[kt], b[0], b[1]);
                    mma_16816hh(s1, aq[kt], b[2], b[3]);
                }
                // p = 2^s directly on packed f16x2 D; result IS the PV A-frag
                uint32_t p00 = ex2h2(s0[0]);   // row qr,  cols j..j+1
                uint32_t p01 = ex2h2(s0[1]);   // row qr+8
                uint32_t p10 = ex2h2(s1[0]);   // row qr,  cols j+8..j+9
                uint32_t p11 = ex2h2(s1[1]);   // row qr+8
                sum2a = __hadd2(sum2a, *(__half2*)&p00);
                sum2a = __hadd2(sum2a, *(__half2*)&p10);
                sum2b = __hadd2(sum2b, *(__half2*)&p01);
                sum2b = __hadd2(sum2b, *(__half2*)&p11);
                pa[4 * nn]     = p00;
                pa[4 * nn + 1] = p01;
                pa[4 * nn + 2] = p10;
                pa[4 * nn + 3] = p11;
            }
            float2 fa = __half22float2(sum2a);
            float2 fb = __half22float2(sum2b);
            l0 += fa.x + fa.y;
            l1 += fb.x + fb.y;

            // P @ V (f16 x f16, f16 accum)
#pragma unroll
            for (int kt = 0; kt < 5; ++kt) {
                const uint32_t* A = &pa[4 * kt];
                const int krow = j0 + kt * 16 + l15;
#pragma unroll
                for (int nn = 0; nn < 4; ++nn) {
                    uint32_t b[4];
                    ldsm_x4_t(b, VS + SWZ128(krow * 128 + nn * 32 + lhi * 16));
                    mma_16816hh(&oh[(nn * 2) * 2],     A, b[0], b[1]);
                    mma_16816hh(&oh[(nn * 2 + 1) * 2], A, b[2], b[3]);
                }
            }
        }

        l0 += __shfl_xor_sync(0xffffffffu, l0, 1);
        l0 += __shfl_xor_sync(0xffffffffu, l0, 2);
        l1 += __shfl_xor_sync(0xffffffffu, l1, 1);
        l1 += __shfl_xor_sync(0xffffffffu, l1, 2);
        const float i0 = 1.f / l0;
        const float i1 = 1.f / l1;
#pragma unroll
        for (int n = 0; n < 8; ++n) {
            int q = q0 + qr;
            int d = n * 8 + l3 * 2;
            size_t idx = base + (size_t)q * 64 + d;
            float2 xr = *(const float2*)&x[idx];
            float2 oc0 = __half22float2(*(__half2*)&oh[2 * n]);
            __half2 y0 = __floats2half2_rn(oc0.x * i0 + xr.x, oc0.y * i0 + xr.y);
            *(uint32_t*)&g_Yh[idx] = *(uint32_t*)&y0;
            size_t idx2 = idx + 8 * 64;
            float2 xr2 = *(const float2*)&x[idx2];
            float2 oc1 = __half22float2(*(__half2*)&oh[2 * n + 1]);
            __half2 y1 = __floats2half2_rn(oc1.x * i1 + xr2.x, oc1.y * i1 + xr2.y);
            *(uint32_t*)&g_Yh[idx2] = *(uint32_t*)&y1;
        }
    }
}

// ---------------------------------------------------------------------------
// LayerNorm: one warp per row, f16 input, fp32 output
// ---------------------------------------------------------------------------
__global__ __launch_bounds__(256) void ln_kernel(
    const float* __restrict__ gamma,
    const float* __restrict__ beta,
    float* __restrict__ out)
{
    const int lane = threadIdx.x & 31;
    const int w    = threadIdx.x >> 5;
    const int row  = blockIdx.x * 8 + w;
    const uint2* y = (const uint2*)(g_Yh + (size_t)row * DIM);

    float4 v[5];
    float s = 0.f, sq = 0.f;
#pragma unroll
    for (int u = 0; u < 5; ++u) {
        uint2 raw = y[lane + 32 * u];
        float2 a = __half22float2(*(__half2*)&raw.x);
        float2 b = __half22float2(*(__half2*)&raw.y);
        v[u] = make_float4(a.x, a.y, b.x, b.y);
        s  += v[u].x + v[u].y + v[u].z + v[u].w;
        sq += v[u].x * v[u].x + v[u].y * v[u].y + v[u].z * v[u].z + v[u].w * v[u].w;
    }
#pragma unroll
    for (int o = 16; o > 0; o >>= 1) {
        s  += __shfl_xor_sync(0xffffffffu, s, o);
        sq += __shfl_xor_sync(0xffffffffu, sq, o);
    }
    const float mu  = s * (1.f / DIM);
    float var = sq * (1.f / DIM) - mu * mu;
    var = fmaxf(var, 0.f);
    const float rinv = rsqrtf(var + 1e-5f);

    float* orow = out + (size_t)row * DIM;
#pragma unroll
    for (int u = 0; u < 5; ++u) {
        float4 g4 = ((const float4*)gamma)[lane + 32 * u];
        float4 b4 = ((const float4*)beta)[lane + 32 * u];
        float4 o;
        o.x = (v[u].x - mu) * rinv * g4.x + b4.x;
        o.y = (v[u].y - mu) * rinv * g4.y + b4.y;
        o.z = (v[u].z - mu) * rinv * g4.z + b4.z;
        o.w = (v[u].w - mu) * rinv * g4.w + b4.w;
        ((float4*)orow)[lane + 32 * u] = o;
    }
}

// ---------------------------------------------------------------------------
extern "C" void kernel_launch(void* const* d_in, const int* in_sizes, int n_in,
                              void* d_out, int out_size)
{
    const float* x     = (const float*)d_in[0];
    const float* Wq    = (const float*)d_in[1];
    const float* Wk    = (const float*)d_in[2];
    const float* Wv    = (const float*)d_in[3];
    const float* gamma = (const float*)d_in[4];
    const float* beta  = (const float*)d_in[5];
    float* out = (float*)d_out;

    cudaFuncSetAttribute(qkv_mma, cudaFuncAttributeMaxDynamicSharedMemorySize, GEMM_SMEM);
    cudaFuncSetAttribute(attn_mma, cudaFuncAttributeMaxDynamicSharedMemorySize, ATT_SMEM);

    cvt_all<<<8600, 256>>>(x, Wq, Wk, Wv);

    dim3 ggrid(NROWS / 128, DIM / 128, 3);
    qkv_mma<<<ggrid, 256, GEMM_SMEM>>>();

    dim3 agrid(NCHUNK, 2);
    attn_mma<<<agrid, 256, ATT_SMEM>>>(x);

    ln_kernel<<<NROWS / 8, 256>>>(gamma, beta, out);
}

// round 14
// speedup vs baseline: 1.0839x; 1.0357x over previous
#include <cuda_runtime.h>
#include <cuda_bf16.h>
#include <cuda_fp16.h>
#include <cstdint>

#define SEQ    400
#define NHEADS 10
#define DK     64
#define NROWS  25600
#define DIM    640
#define CHUNK  (SEQ*DK)
#define NCHUNK ((NROWS/SEQ)*NHEADS)  // 640

// exp(s*0.125) = 2^(s*0.125*log2e); folded into Wq at convert time
#define QSCALE 0.180336878f

// Scratch (static __device__ arrays: the sanctioned no-alloc workaround)
__device__ __half        g_Yh[(size_t)NROWS * DIM];   // f16 intermediate Y
__device__ __nv_bfloat16 g_Xb[(size_t)NROWS * DIM];
__device__ __nv_bfloat16 g_Wb[(size_t)3 * DIM * DIM];
__device__ __half        g_Qh[(size_t)NROWS * DIM];
__device__ __half        g_Kh[(size_t)NROWS * DIM];
__device__ __half        g_Vh[(size_t)NROWS * DIM];

// ---------------------------------------------------------------------------
// helpers
// ---------------------------------------------------------------------------
__device__ __forceinline__ uint32_t smem_u32(const void* p) {
    uint32_t a;
    asm("{ .reg .u64 t; cvta.to.shared.u64 t, %1; cvt.u32.u64 %0, t; }" : "=r"(a) : "l"(p));
    return a;
}
#define SWZ128(o) ((o) ^ (((o) >> 3) & 0x70))

__device__ __forceinline__ void cp_async16(uint32_t dst, const void* src) {
    asm volatile("cp.async.cg.shared.global [%0], [%1], 16;" :: "r"(dst), "l"(src));
}
#define CP_COMMIT() asm volatile("cp.async.commit_group;" ::: "memory")
#define CP_WAIT(n)  asm volatile("cp.async.wait_group %0;" :: "n"(n) : "memory")

__device__ __forceinline__ void ldsm_x4(uint32_t* r, uint32_t addr) {
    asm volatile("ldmatrix.sync.aligned.m8n8.x4.shared.b16 {%0,%1,%2,%3}, [%4];"
                 : "=r"(r[0]), "=r"(r[1]), "=r"(r[2]), "=r"(r[3]) : "r"(addr));
}
__device__ __forceinline__ void ldsm_x4_t(uint32_t* r, uint32_t addr) {
    asm volatile("ldmatrix.sync.aligned.m8n8.x4.trans.shared.b16 {%0,%1,%2,%3}, [%4];"
                 : "=r"(r[0]), "=r"(r[1]), "=r"(r[2]), "=r"(r[3]) : "r"(addr));
}
// bf16 inputs, fp32 accum (QKV GEMM)
__device__ __forceinline__ void mma_16816(float* c, const uint32_t* a,
                                          uint32_t b0, uint32_t b1) {
    asm volatile("mma.sync.aligned.m16n8k16.row.col.f32.bf16.bf16.f32 "
                 "{%0,%1,%2,%3}, {%4,%5,%6,%7}, {%8,%9}, {%0,%1,%2,%3};"
                 : "+f"(c[0]), "+f"(c[1]), "+f"(c[2]), "+f"(c[3])
                 : "r"(a[0]), "r"(a[1]), "r"(a[2]), "r"(a[3]), "r"(b0), "r"(b1));
}
// f16 inputs, f16 accum (attention; packed D)
__device__ __forceinline__ void mma_16816hh(uint32_t* c, const uint32_t* a,
                                            uint32_t b0, uint32_t b1) {
    asm volatile("mma.sync.aligned.m16n8k16.row.col.f16.f16.f16.f16 "
                 "{%0,%1}, {%2,%3,%4,%5}, {%6,%7}, {%0,%1};"
                 : "+r"(c[0]), "+r"(c[1])
                 : "r"(a[0]), "r"(a[1]), "r"(a[2]), "r"(a[3]), "r"(b0), "r"(b1));
}
__device__ __forceinline__ uint32_t ex2h2(uint32_t h) {
    uint32_t r;
    asm("ex2.approx.f16x2 %0, %1;" : "=r"(r) : "r"(h));
    return r;
}

// ---------------------------------------------------------------------------
// fused fp32 -> bf16 converts: x then Wq/Wk/Wv (one launch)
// ---------------------------------------------------------------------------
__global__ __launch_bounds__(256) void cvt_all(const float* __restrict__ x,
                                               const float* __restrict__ Wq,
                                               const float* __restrict__ Wk,
                                               const float* __restrict__ Wv) {
    const size_t XB = 8000;
    const size_t WB = 200;
    size_t b = blockIdx.x;
    const float* src;
    __nv_bfloat16* dst;
    float sc = 1.0f;
    size_t i;
    if (b < XB) {
        i = (b * 256 + threadIdx.x) * 8;
        src = x; dst = g_Xb;
    } else {
        size_t wb = b - XB;
        int z = (int)(wb / WB);
        i = ((wb - (size_t)z * WB) * 256 + threadIdx.x) * 8;
        src = (z == 0) ? Wq : (z == 1) ? Wk : Wv;
        dst = g_Wb + (size_t)z * DIM * DIM;
        if (z == 0) sc = QSCALE;
    }
    float4 f0 = *(const float4*)(src + i);
    float4 f1 = *(const float4*)(src + i + 4);
    __nv_bfloat162 p0 = __floats2bfloat162_rn(f0.x * sc, f0.y * sc);
    __nv_bfloat162 p1 = __floats2bfloat162_rn(f0.z * sc, f0.w * sc);
    __nv_bfloat162 p2 = __floats2bfloat162_rn(f1.x * sc, f1.y * sc);
    __nv_bfloat162 p3 = __floats2bfloat162_rn(f1.z * sc, f1.w * sc);
    uint4 o;
    o.x = *(uint32_t*)&p0; o.y = *(uint32_t*)&p1;
    o.z = *(uint32_t*)&p2; o.w = *(uint32_t*)&p3;
    *(uint4*)(dst + i) = o;
}

// ---------------------------------------------------------------------------
// QKV GEMM via mma.sync (HMMA bf16, fp32 accum) -> f16 Q/K/V.
// CTA tile 128x128, BK=64, 8 warps 4x2. 3-stage cp.async pipeline. 96KB smem.
// ---------------------------------------------------------------------------
#define GEMM_SMEM (3 * 32768)

__global__ __launch_bounds__(256, 2) void qkv_mma() {
    extern __shared__ char smem[];
    const int tid  = threadIdx.x;
    const int lane = tid & 31;
    const int wid  = tid >> 5;
    const int wm   = wid & 3;
    const int wn   = wid >> 2;
    const int z    = blockIdx.z;
    const int n0   = blockIdx.x * 128;
    const int m0   = blockIdx.y * 128;
    const __nv_bfloat16* Xpt = g_Xb + (size_t)n0 * DIM;
    const __nv_bfloat16* Wpt = g_Wb + (size_t)z * DIM * DIM + (size_t)m0 * DIM;
    const uint32_t sbase = smem_u32(smem);

    const int lr = tid >> 3;
    const int lcc = tid & 7;

    float acc[2][8][4];
#pragma unroll
    for (int i = 0; i < 2; ++i)
#pragma unroll
        for (int j = 0; j < 8; ++j)
#pragma unroll
            for (int k = 0; k < 4; ++k) acc[i][j][k] = 0.f;

    auto issue = [&](int c, int b) {
        const __nv_bfloat16* xs = Xpt + c * 64;
        const __nv_bfloat16* ws = Wpt + c * 64;
        const uint32_t stg = sbase + b * 32768;
#pragma unroll
        for (int i = 0; i < 4; ++i) {
            int r = lr + i * 32;
            uint32_t off = SWZ128(r * 128 + lcc * 16);
            cp_async16(stg + off, xs + (size_t)r * DIM + lcc * 8);
            cp_async16(stg + 16384 + off, ws + (size_t)r * DIM + lcc * 8);
        }
        CP_COMMIT();
    };

    issue(0, 0);
    issue(1, 1);

    const int arow = lane & 15;
    const int akb  = (lane >> 4) * 16;
    const int brow = (lane & 7) + ((lane >> 4) << 3);
    const int bkb  = ((lane >> 3) & 1) * 16;

    for (int c = 0; c < 10; ++c) {
        if (c == 9) { CP_WAIT(0); } else { CP_WAIT(1); }
        __syncthreads();
        if (c < 8) issue(c + 2, (c + 2) % 3);

        const uint32_t stg = sbase + (c % 3) * 32768;
        const uint32_t xb = stg;
        const uint32_t wb = stg + 16384;
#pragma unroll
        for (int ks = 0; ks < 4; ++ks) {
            uint32_t a[2][4];
#pragma unroll
            for (int i = 0; i < 2; ++i)
                ldsm_x4(a[i], xb + SWZ128((wm * 32 + i * 16 + arow) * 128 + ks * 32 + akb));
            uint32_t bf[4][4];
#pragma unroll
            for (int j = 0; j < 4; ++j)
                ldsm_x4(bf[j], wb + SWZ128((wn * 64 + j * 16 + brow) * 128 + ks * 32 + bkb));
#pragma unroll
            for (int i = 0; i < 2; ++i)
#pragma unroll
                for (int jj = 0; jj < 8; ++jj)
                    mma_16816(acc[i][jj], a[i], bf[jj >> 1][(jj & 1) * 2],
                              bf[jj >> 1][(jj & 1) * 2 + 1]);
        }
    }

    const int qr = lane >> 2;
    const int qc = (lane & 3) * 2;
    __half* Cz = (z == 0) ? g_Qh : (z == 1) ? g_Kh : g_Vh;
#pragma unroll
    for (int i = 0; i < 2; ++i)
#pragma unroll
        for (int jj = 0; jj < 8; ++jj) {
            int n = n0 + wm * 32 + i * 16 + qr;
            int m = m0 + wn * 64 + jj * 8 + qc;
            __half2 lo = __floats2half2_rn(acc[i][jj][0], acc[i][jj][1]);
            __half2 hi = __floats2half2_rn(acc[i][jj][2], acc[i][jj][3]);
            *(uint32_t*)&Cz[(size_t)n * DIM + m] = *(uint32_t*)&lo;
            *(uint32_t*)&Cz[(size_t)(n + 8) * DIM + m] = *(uint32_t*)&hi;
        }
}

// ---------------------------------------------------------------------------
// FlashAttention-style attention via mma.sync, v10:
//  - m32 per warp: 2 q-tiles share every K/V ldmatrix (crossbar bytes halved)
//  - PV fused per nn-block (no max-softmax => any j accumulation order);
//    P lives 4 regs/tile transiently
//  - 25 tiles = 12 pairs + 1 single; items 0..12 over grid(640,2) x 8 warps
//  - all f16 HMMA; ex2.approx.f16x2 directly on packed S frags
// ---------------------------------------------------------------------------
#define VOFF2 52224                  // 51*1024, 1024-aligned
#define ATT_SMEM (VOFF2 + 51200)     // 103424

__global__ __launch_bounds__(256, 2) void attn_mma(const float* __restrict__ x)
{
    extern __shared__ char sm[];
    const int tid  = threadIdx.x;
    const int lane = tid & 31;
    const int w    = tid >> 5;
    const int chunk = blockIdx.x;
    const int half  = blockIdx.y;
    const size_t base = (size_t)chunk * CHUNK;
    const uint32_t KS = smem_u32(sm);
    const uint32_t VS = KS + VOFF2;

    // stage Km (raw-reshape layout [d][j], 816B padded rows) and V f16 (SW128)
    {
        const uint4* Kg = (const uint4*)(g_Kh + base);
        const uint4* Vg = (const uint4*)(g_Vh + base);
        for (int i = tid; i < 3200; i += 256) {
            int d = i / 50;
            int j = (i - d * 50) * 8;
            cp_async16(KS + d * 816 + j * 2, Kg + i);
            int row = i >> 3, cc = i & 7;
            cp_async16(VS + SWZ128(row * 128 + cc * 16), Vg + i);
        }
        CP_COMMIT();
        CP_WAIT(0);
    }
    __syncthreads();

    const int item = half * 7 + w;     // 0..12 valid (13 items: 12 pairs + 1)
    if (item > 12) return;
    const bool two = (item < 12);

    const int qr  = lane >> 2;
    const int l3  = lane & 3;
    const int l15 = lane & 15;
    const int lhi = lane >> 4;
    const uint32_t* Qg = (const uint32_t*)(g_Qh + base);

    const int q0 = item * 32;          // tile0 rows [q0, q0+16)
                                       // tile1 rows [q0+16, q0+32) if two

    // A-frags for both tiles, straight from gmem
    uint32_t aq0[4][4], aq1[4][4];
    {
        const int r0 = (q0 + qr) * 32;
        const int r1 = r0 + 8 * 32;
#pragma unroll
        for (int kt = 0; kt < 4; ++kt) {
            aq0[kt][0] = Qg[r0 + kt * 8 + l3];
            aq0[kt][1] = Qg[r1 + kt * 8 + l3];
            aq0[kt][2] = Qg[r0 + kt * 8 + l3 + 4];
            aq0[kt][3] = Qg[r1 + kt * 8 + l3 + 4];
        }
        if (two) {
            const int r2 = r0 + 16 * 32;
            const int r3 = r2 + 8 * 32;
#pragma unroll
            for (int kt = 0; kt < 4; ++kt) {
                aq1[kt][0] = Qg[r2 + kt * 8 + l3];
                aq1[kt][1] = Qg[r3 + kt * 8 + l3];
                aq1[kt][2] = Qg[r2 + kt * 8 + l3 + 4];
                aq1[kt][3] = Qg[r3 + kt * 8 + l3 + 4];
            }
        }
    }

    float l00 = 0.f, l01 = 0.f, l10 = 0.f, l11 = 0.f;
    uint32_t oh0[16], oh1[16];
#pragma unroll
    for (int n = 0; n < 16; ++n) { oh0[n] = 0u; oh1[n] = 0u; }

#pragma unroll
    for (int jc = 0; jc < 5; ++jc) {
        const int j0 = jc * 80;
        __half2 sa0 = __floats2half2_rn(0.f, 0.f);
        __half2 sb0 = sa0, sa1 = sa0, sb1 = sa0;

#pragma unroll
        for (int nn = 0; nn < 5; ++nn) {
            // ---- S for both tiles over this n16 j-block ----
            uint32_t s00[2] = {0u, 0u}, s01[2] = {0u, 0u};
            uint32_t s10[2] = {0u, 0u}, s11[2] = {0u, 0u};
#pragma unroll
            for (int kt = 0; kt < 4; ++kt) {
                uint32_t bk[4];
                ldsm_x4_t(bk, KS + (kt * 16 + l15) * 816 +
                              (j0 + nn * 16 + lhi * 8) * 2);
                mma_16816hh(s00, aq0[kt], bk[0], bk[1]);
                mma_16816hh(s01, aq0[kt], bk[2], bk[3]);
                if (two) {
                    mma_16816hh(s10, aq1[kt], bk[0], bk[1]);
                    mma_16816hh(s11, aq1[kt], bk[2], bk[3]);
                }
            }
            // ---- p = 2^s, packed; result IS the PV A-frag ----
            uint32_t A0[4], A1[4];
            A0[0] = ex2h2(s00[0]); A0[1] = ex2h2(s00[1]);
            A0[2] = ex2h2(s01[0]); A0[3] = ex2h2(s01[1]);
            sa0 = __hadd2(sa0, __hadd2(*(__half2*)&A0[0], *(__half2*)&A0[2]));
            sb0 = __hadd2(sb0, __hadd2(*(__half2*)&A0[1], *(__half2*)&A0[3]));
            if (two) {
                A1[0] = ex2h2(s10[0]); A1[1] = ex2h2(s10[1]);
                A1[2] = ex2h2(s11[0]); A1[3] = ex2h2(s11[1]);
                sa1 = __hadd2(sa1, __hadd2(*(__half2*)&A1[0], *(__half2*)&A1[2]));
                sb1 = __hadd2(sb1, __hadd2(*(__half2*)&A1[1], *(__half2*)&A1[3]));
            }
            // ---- PV for this j-block, both tiles share V frags ----
            const int krow = j0 + nn * 16 + l15;
#pragma unroll
            for (int dd = 0; dd < 4; ++dd) {
                uint32_t bv[4];
                ldsm_x4_t(bv, VS + SWZ128(krow * 128 + dd * 32 + lhi * 16));
                mma_16816hh(&oh0[4 * dd],     A0, bv[0], bv[1]);
                mma_16816hh(&oh0[4 * dd + 2], A0, bv[2], bv[3]);
                if (two) {
                    mma_16816hh(&oh1[4 * dd],     A1, bv[0], bv[1]);
                    mma_16816hh(&oh1[4 * dd + 2], A1, bv[2], bv[3]);
                }
            }
        }
        float2 fa = __half22float2(sa0);
        float2 fb = __half22float2(sb0);
        l00 += fa.x + fa.y;
        l01 += fb.x + fb.y;
        if (two) {
            float2 fc = __half22float2(sa1);
            float2 fd = __half22float2(sb1);
            l10 += fc.x + fc.y;
            l11 += fd.x + fd.y;
        }
    }

    // row sums across col quads
    l00 += __shfl_xor_sync(0xffffffffu, l00, 1);
    l00 += __shfl_xor_sync(0xffffffffu, l00, 2);
    l01 += __shfl_xor_sync(0xffffffffu, l01, 1);
    l01 += __shfl_xor_sync(0xffffffffu, l01, 2);
    l10 += __shfl_xor_sync(0xffffffffu, l10, 1);
    l10 += __shfl_xor_sync(0xffffffffu, l10, 2);
    l11 += __shfl_xor_sync(0xffffffffu, l11, 1);
    l11 += __shfl_xor_sync(0xffffffffu, l11, 2);

    const float i00 = 1.f / l00;
    const float i01 = 1.f / l01;
#pragma unroll
    for (int n = 0; n < 8; ++n) {
        int q = q0 + qr;
        int d = n * 8 + l3 * 2;
        size_t idx = base + (size_t)q * 64 + d;
        float2 xr = *(const float2*)&x[idx];
        float2 oc0 = __half22float2(*(__half2*)&oh0[2 * n]);
        __half2 y0 = __floats2half2_rn(oc0.x * i00 + xr.x, oc0.y * i00 + xr.y);
        *(uint32_t*)&g_Yh[idx] = *(uint32_t*)&y0;
        size_t idx2 = idx + 8 * 64;
        float2 xr2 = *(const float2*)&x[idx2];
        float2 oc1 = __half22float2(*(__half2*)&oh0[2 * n + 1]);
        __half2 y1 = __floats2half2_rn(oc1.x * i01 + xr2.x, oc1.y * i01 + xr2.y);
        *(uint32_t*)&g_Yh[idx2] = *(uint32_t*)&y1;
    }
    if (two) {
        const float i10 = 1.f / l10;
        const float i11 = 1.f / l11;
#pragma unroll
        for (int n = 0; n < 8; ++n) {
            int q = q0 + 16 + qr;
            int d = n * 8 + l3 * 2;
            size_t idx = base + (size_t)q * 64 + d;
            float2 xr = *(const float2*)&x[idx];
            float2 oc0 = __half22float2(*(__half2*)&oh1[2 * n]);
            __half2 y0 = __floats2half2_rn(oc0.x * i10 + xr.x, oc0.y * i10 + xr.y);
            *(uint32_t*)&g_Yh[idx] = *(uint32_t*)&y0;
            size_t idx2 = idx + 8 * 64;
            float2 xr2 = *(const float2*)&x[idx2];
            float2 oc1 = __half22float2(*(__half2*)&oh1[2 * n + 1]);
            __half2 y1 = __floats2half2_rn(oc1.x * i11 + xr2.x, oc1.y * i11 + xr2.y);
            *(uint32_t*)&g_Yh[idx2] = *(uint32_t*)&y1;
        }
    }
}

// ---------------------------------------------------------------------------
// LayerNorm: one warp per row, f16 input, fp32 output
// ---------------------------------------------------------------------------
__global__ __launch_bounds__(256) void ln_kernel(
    const float* __restrict__ gamma,
    const float* __restrict__ beta,
    float* __restrict__ out)
{
    const int lane = threadIdx.x & 31;
    const int w    = threadIdx.x >> 5;
    const int row  = blockIdx.x * 8 + w;
    const uint2* y = (const uint2*)(g_Yh + (size_t)row * DIM);

    float4 v[5];
    float s = 0.f, sq = 0.f;
#pragma unroll
    for (int u = 0; u < 5; ++u) {
        uint2 raw = y[lane + 32 * u];
        float2 a = __half22float2(*(__half2*)&raw.x);
        float2 b = __half22float2(*(__half2*)&raw.y);
        v[u] = make_float4(a.x, a.y, b.x, b.y);
        s  += v[u].x + v[u].y + v[u].z + v[u].w;
        sq += v[u].x * v[u].x + v[u].y * v[u].y + v[u].z * v[u].z + v[u].w * v[u].w;
    }
#pragma unroll
    for (int o = 16; o > 0; o >>= 1) {
        s  += __shfl_xor_sync(0xffffffffu, s, o);
        sq += __shfl_xor_sync(0xffffffffu, sq, o);
    }
    const float mu  = s * (1.f / DIM);
    float var = sq * (1.f / DIM) - mu * mu;
    var = fmaxf(var, 0.f);
    const float rinv = rsqrtf(var + 1e-5f);

    float* orow = out + (size_t)row * DIM;
#pragma unroll
    for (int u = 0; u < 5; ++u) {
        float4 g4 = ((const float4*)gamma)[lane + 32 * u];
        float4 b4 = ((const float4*)beta)[lane + 32 * u];
        float4 o;
        o.x = (v[u].x - mu) * rinv * g4.x + b4.x;
        o.y = (v[u].y - mu) * rinv * g4.y + b4.y;
        o.z = (v[u].z - mu) * rinv * g4.z + b4.z;
        o.w = (v[u].w - mu) * rinv * g4.w + b4.w;
        ((float4*)orow)[lane + 32 * u] = o;
    }
}

// ---------------------------------------------------------------------------
extern "C" void kernel_launch(void* const* d_in, const int* in_sizes, int n_in,
                              void* d_out, int out_size)
{
    const float* x     = (const float*)d_in[0];
    const float* Wq    = (const float*)d_in[1];
    const float* Wk    = (const float*)d_in[2];
    const float* Wv    = (const float*)d_in[3];
    const float* gamma = (const float*)d_in[4];
    const float* beta  = (const float*)d_in[5];
    float* out = (float*)d_out;

    cudaFuncSetAttribute(qkv_mma, cudaFuncAttributeMaxDynamicSharedMemorySize, GEMM_SMEM);
    cudaFuncSetAttribute(attn_mma, cudaFuncAttributeMaxDynamicSharedMemorySize, ATT_SMEM);

    cvt_all<<<8600, 256>>>(x, Wq, Wk, Wv);

    dim3 ggrid(NROWS / 128, DIM / 128, 3);
    qkv_mma<<<ggrid, 256, GEMM_SMEM>>>();

    dim3 agrid(NCHUNK, 2);
    attn_mma<<<agrid, 256, ATT_SMEM>>>(x);

    ln_kernel<<<NROWS / 8, 256>>>(gamma, beta, out);
}